// round 13
// baseline (speedup 1.0000x reference)
#include <cuda_runtime.h>
#include <cuda_bf16.h>
#include <cstdint>

#define BB 2
#define QL 1024
#define ML 1024
#define KLEN 2048
#define EMB 1024
#define NH 16
#define DH 64

typedef __nv_bfloat16 bf16;
typedef __nv_bfloat162 bf162;

// scale folded into Q and BD: (1/sqrt(1024)) * log2(e)
#define SCL2 (0.03125f * 1.4426950408889634f)

// ---------------- scratch (static device, allocation-free) ----------------
__device__ bf16 g_Qh[BB * QL * EMB];
__device__ bf16 g_Kh[BB * KLEN * EMB];
__device__ bf16 g_Vh[BB * KLEN * EMB];
__device__ bf16 g_Rh[KLEN * EMB];
__device__ bf16 g_BDh[(size_t)BB * NH * QL * KLEN];
__device__ float g_AOp[2][BB * QL * EMB];   // split-KV partial O (unnormalized)
__device__ float g_Lp[2][BB * NH * QL];     // split-KV partial row sums
__device__ float g_Linv[BB * NH * QL];      // 1/(l0+l1)
__device__ float g_X[BB * QL * EMB];
__device__ bf16 g_WTb[5ull * 1024 * 1024];

__device__ __forceinline__ uint32_t smem_u32(const void* p) {
    uint32_t a;
    asm("{ .reg .u64 t; cvta.to.shared.u64 t, %1; cvt.u32.u64 %0, t; }" : "=r"(a) : "l"(p));
    return a;
}
__device__ __forceinline__ uint32_t bf16x2_of(float lo, float hi) {
    uint32_t o;
    asm("cvt.rn.bf16x2.f32 %0, %1, %2;" : "=r"(o) : "f"(hi), "f"(lo));
    return o;
}
__device__ __forceinline__ float2 f2_of_bf16x2(uint32_t w) {
    bf162 t = *reinterpret_cast<bf162*>(&w);
    return __bfloat1622float2(t);
}
__device__ __forceinline__ float ex2f(float x) {
    float y;
    asm("ex2.approx.f32 %0, %1;" : "=f"(y) : "f"(x));
    return y;
}
#define MMA16816(C, A0, A1, A2, A3, B0, B1) \
    asm volatile("mma.sync.aligned.m16n8k16.row.col.f32.bf16.bf16.f32 " \
        "{%0,%1,%2,%3}, {%4,%5,%6,%7}, {%8,%9}, {%0,%1,%2,%3};" \
        : "+f"((C)[0]), "+f"((C)[1]), "+f"((C)[2]), "+f"((C)[3]) \
        : "r"(A0), "r"(A1), "r"(A2), "r"(A3), "r"(B0), "r"(B1))
#define LDSM_X4(d0, d1, d2, d3, addr) \
    asm volatile("ldmatrix.sync.aligned.m8n8.x4.shared.b16 {%0,%1,%2,%3}, [%4];" \
        : "=r"(d0), "=r"(d1), "=r"(d2), "=r"(d3) : "r"(addr))
#define LDSM_X4_T(d0, d1, d2, d3, addr) \
    asm volatile("ldmatrix.sync.aligned.m8n8.x4.trans.shared.b16 {%0,%1,%2,%3}, [%4];" \
        : "=r"(d0), "=r"(d1), "=r"(d2), "=r"(d3) : "r"(addr))
#define CPA16(dst, src) \
    asm volatile("cp.async.cg.shared.global [%0], [%1], 16;" :: "r"(dst), "l"(src) : "memory")
#define CP_COMMIT() asm volatile("cp.async.commit_group;" ::: "memory")
#define CP_WAIT0()  asm volatile("cp.async.wait_group 0;" ::: "memory")
#define CP_WAIT1()  asm volatile("cp.async.wait_group 1;" ::: "memory")

// ---------------- weight transpose + bf16 convert ----------------
__global__ __launch_bounds__(256) void transposeW(
    const float* __restrict__ w0, const float* __restrict__ w1,
    const float* __restrict__ w2, const float* __restrict__ w3,
    const float* __restrict__ w4)
{
    __shared__ float t[32][33];
    const float* src;
    switch (blockIdx.z) {
        case 0: src = w0; break;
        case 1: src = w1; break;
        case 2: src = w2; break;
        case 3: src = w3; break;
        default: src = w4; break;
    }
    bf16* dst = g_WTb + ((size_t)blockIdx.z << 20);
    int tx = threadIdx.x & 31, ty = threadIdx.x >> 5;
    int x = blockIdx.x * 32 + tx;
    int y = blockIdx.y * 32 + ty;
#pragma unroll
    for (int j = 0; j < 32; j += 8)
        t[ty + j][tx] = src[(size_t)(y + j) * EMB + x];
    __syncthreads();
    x = blockIdx.y * 32 + tx;
    y = blockIdx.x * 32 + ty;
#pragma unroll
    for (int j = 0; j < 32; j += 8)
        dst[(size_t)(y + j) * EMB + x] = __float2bfloat16(t[tx][ty + j]);
}

// ================= shared GEMM body (128x128 tile, ldmatrix, cp.async) =================
// mode 0: A rows direct (fp32). mode 1: gather cat(member=A, w=A2).
// mode 2: A = (g_AOp[0] + g_AOp[1]) * g_Linv  (split-KV combine fused in).
template <bool OBF>
__device__ __forceinline__ void gemm_tile_body(
    const float* __restrict__ A, const float* __restrict__ A2,
    const bf16* __restrict__ WT,
    void* C0v, void* C1v, const float* __restrict__ resid,
    int mode, int m0, int n0, uint32_t* smw)
{
    const uint32_t sbase = smem_u32(smw);
    const int tid = threadIdx.x;
    const int lane = tid & 31, wid = tid >> 5;
    const int wm = wid >> 1, wn = wid & 1;
    const int g = lane >> 2, tig = lane & 3;

    const float* ap[4];
    const float* ap2[4];
    int lidx[4];
    uint32_t swA[4];
#pragma unroll
    for (int u = 0; u < 4; u++) {
        int f4 = tid + 256 * u;
        int rr = f4 >> 3, c4 = f4 & 7;
        int m = m0 + rr;
        const float* arow;
        if (mode == 0) {
            arow = A + (size_t)m * EMB;
            ap2[u] = nullptr; lidx[u] = 0;
        } else if (mode == 1) {
            int b = m >> 11, t = m & 2047;
            arow = (t < ML) ? (A + ((size_t)b * ML + t) * EMB)
                            : (A2 + ((size_t)b * QL + (t - ML)) * EMB);
            ap2[u] = nullptr; lidx[u] = 0;
        } else {
            arow = g_AOp[0] + (size_t)m * EMB;
            ap2[u] = g_AOp[1] + (size_t)m * EMB + c4 * 4;
            int b = m >> 10, q = m & 1023;
            lidx[u] = b * NH * QL + q;
        }
        ap[u] = arow + c4 * 4;
        swA[u] = (uint32_t)(rr * 20 + c4 * 2);
    }
    const bf16* bp[2];
    uint32_t dstB[2];
#pragma unroll
    for (int v = 0; v < 2; v++) {
        int f16 = tid + 256 * v;
        int rr = f16 >> 2, c16 = f16 & 3;
        bp[v] = WT + (size_t)(n0 + rr) * EMB + c16 * 8;
        dstB[v] = sbase + 10240 + (uint32_t)(rr * 80 + c16 * 16);
    }

    float4 ra[4];
#define LDGA(k0) do { \
        if (mode == 2) { \
            _Pragma("unroll") for (int u = 0; u < 4; u++) { \
                float4 v0 = *(const float4*)(ap[u] + (k0)); \
                float4 v1 = *(const float4*)(ap2[u] + (k0)); \
                float inv = g_Linv[lidx[u] + ((k0) >> 6) * QL]; \
                ra[u].x = (v0.x + v1.x) * inv; \
                ra[u].y = (v0.y + v1.y) * inv; \
                ra[u].z = (v0.z + v1.z) * inv; \
                ra[u].w = (v0.w + v1.w) * inv; \
            } \
        } else { \
            _Pragma("unroll") for (int u = 0; u < 4; u++) ra[u] = *(const float4*)(ap[u] + (k0)); \
        } \
    } while (0)
#define STSA(buf) do { \
        uint32_t* Aw_ = smw + (buf) * 5120; \
        _Pragma("unroll") for (int u = 0; u < 4; u++) { \
            Aw_[swA[u]]     = bf16x2_of(ra[u].x, ra[u].y); \
            Aw_[swA[u] + 1] = bf16x2_of(ra[u].z, ra[u].w); \
        } \
    } while (0)
#define CPB(buf, k0) do { \
        _Pragma("unroll") for (int v = 0; v < 2; v++) \
            CPA16(dstB[v] + (buf) * 20480, bp[v] + (k0)); \
        CP_COMMIT(); \
    } while (0)

    const uint32_t aLd = sbase + (uint32_t)((wm * 32 + (lane & 15)) * 80 + (lane & 16));
    const uint32_t bLd = sbase + 10240 + (uint32_t)((wn * 64 + (lane & 15)) * 80 + (lane & 16));

    float c[2][8][4];
#pragma unroll
    for (int mf = 0; mf < 2; mf++)
#pragma unroll
        for (int nf = 0; nf < 8; nf++)
#pragma unroll
            for (int e = 0; e < 4; e++) c[mf][nf][e] = 0.f;

    LDGA(0);
    CPB(0, 0);
    STSA(0);
    CP_WAIT0();
    __syncthreads();

    for (int it = 0; it < 32; it++) {
        if (it + 1 < 32) {
            LDGA((it + 1) * 32);
            CPB((it + 1) & 1, (it + 1) * 32);
        }
        const uint32_t bufB = (uint32_t)(it & 1) * 20480;
#pragma unroll
        for (int ks = 0; ks < 2; ks++) {
            uint32_t a0, a1, a2, a3, a4, a5, a6, a7;
            LDSM_X4(a0, a1, a2, a3, aLd + bufB + ks * 32);
            LDSM_X4(a4, a5, a6, a7, aLd + bufB + 1280 + ks * 32);
#pragma unroll
            for (int nf2 = 0; nf2 < 4; nf2++) {
                uint32_t b0, b1, b2, b3;
                LDSM_X4(b0, b1, b2, b3, bLd + bufB + nf2 * 1280 + ks * 32);
                MMA16816(c[0][2 * nf2],     a0, a1, a2, a3, b0, b2);
                MMA16816(c[0][2 * nf2 + 1], a0, a1, a2, a3, b1, b3);
                MMA16816(c[1][2 * nf2],     a4, a5, a6, a7, b0, b2);
                MMA16816(c[1][2 * nf2 + 1], a4, a5, a6, a7, b1, b3);
            }
        }
        if (it + 1 < 32) STSA((it + 1) & 1);
        CP_WAIT0();
        __syncthreads();
    }

    if (OBF) {
        bf16* C = (bf16*)((n0 < 1024) ? C0v : C1v);
        int col0 = (n0 & 1023) + wn * 64;
#pragma unroll
        for (int mf = 0; mf < 2; mf++) {
            int r0 = m0 + wm * 32 + mf * 16 + g;
#pragma unroll
            for (int nf = 0; nf < 8; nf++) {
                int col = col0 + nf * 8 + tig * 2;
                *(uint32_t*)&C[(size_t)r0 * EMB + col] = bf16x2_of(c[mf][nf][0], c[mf][nf][1]);
                *(uint32_t*)&C[(size_t)(r0 + 8) * EMB + col] = bf16x2_of(c[mf][nf][2], c[mf][nf][3]);
            }
        }
    } else {
        float* C = (float*)C0v;
#pragma unroll
        for (int mf = 0; mf < 2; mf++) {
            int r0 = m0 + wm * 32 + mf * 16 + g;
#pragma unroll
            for (int nf = 0; nf < 8; nf++) {
                int col = n0 + wn * 64 + nf * 8 + tig * 2;
                float2 v0 = make_float2(c[mf][nf][0], c[mf][nf][1]);
                float2 v1 = make_float2(c[mf][nf][2], c[mf][nf][3]);
                if (resid) {
                    float2 a0 = *(const float2*)(resid + (size_t)r0 * EMB + col);
                    float2 a1 = *(const float2*)(resid + (size_t)(r0 + 8) * EMB + col);
                    v0.x += a0.x; v0.y += a0.y;
                    v1.x += a1.x; v1.y += a1.y;
                }
                *(float2*)(C + (size_t)r0 * EMB + col) = v0;
                *(float2*)(C + (size_t)(r0 + 8) * EMB + col) = v1;
            }
        }
    }
#undef LDGA
#undef STSA
#undef CPB
}

// ---------------- fused projection GEMM: Q + KV + R in one launch ----------------
__global__ __launch_bounds__(256, 2) void proj_gemm(
    const float* __restrict__ w, const float* __restrict__ member,
    const float* __restrict__ r)
{
    __shared__ uint32_t smw[10240];
    const int t = blockIdx.x;
    const float *A, *A2 = nullptr;
    const bf16* WT;
    void *C0, *C1 = nullptr;
    int mode, m0, n0;
    if (t < 128) {
        A = w; WT = g_WTb; C0 = g_Qh; mode = 0;
        m0 = (t >> 3) * 128; n0 = (t & 7) * 128;
    } else if (t < 640) {
        int u = t - 128;
        A = member; A2 = w; WT = g_WTb + (1u << 20); C0 = g_Kh; C1 = g_Vh; mode = 1;
        m0 = (u >> 4) * 128; n0 = (u & 15) * 128;
    } else {
        int u = t - 640;
        A = r; WT = g_WTb + (3u << 20); C0 = g_Rh; mode = 0;
        m0 = (u >> 3) * 128; n0 = (u & 7) * 128;
    }
    gemm_tile_body<true>(A, A2, WT, C0, C1, nullptr, mode, m0, n0, smw);
}

// ---------------- Wo GEMM + fused split-KV combine + residual (fp32 out) ----------------
__global__ __launch_bounds__(256, 2) void wo_gemm(const float* __restrict__ resid)
{
    __shared__ uint32_t smw[10240];
    const int m0 = blockIdx.y * 128, n0 = blockIdx.x * 128;
    gemm_tile_body<false>(nullptr, nullptr, g_WTb + (4u << 20), g_X, nullptr,
                          resid, 2, m0, n0, smw);
}

// ---------------- inverse row sums: g_Linv = 1/(l0+l1) ----------------
__global__ __launch_bounds__(256) void linv_kernel()
{
    int i = blockIdx.x * 256 + threadIdx.x;   // 32768 total
    g_Linv[i] = 1.0f / (g_Lp[0][i] + g_Lp[1][i]);
}

// ---------------- BD via bf16 mma (ldmatrix), pre-shifted band write (x SCL2) ----------------
__global__ __launch_bounds__(256, 2) void bd_mma(const float* __restrict__ rrb)
{
    const int pt = blockIdx.x, it = blockIdx.y, bh = blockIdx.z;
    const int i0 = it * 128, p0 = pt * 64;
    if (i0 + p0 < 833) return;
    const int b = bh >> 4, h = bh & 15;

    __shared__ uint32_t sm[6912];
    const uint32_t sbase = smem_u32(sm);
    const uint32_t Rb = sbase + 18432;
    const int tid = threadIdx.x, lane = tid & 31, wm = tid >> 5;
    const int g = lane >> 2, tig = lane & 3;

#pragma unroll
    for (int u = 0; u < 2; u++) {
        int f = tid + 256 * u;
        int row = f >> 3, c16 = f & 7;
        CPA16(Rb + row * 144 + c16 * 16,
              g_Rh + ((size_t)(p0 + row)) * EMB + h * DH + c16 * 8);
    }
    CP_COMMIT();

    const float2* bias2 = (const float2*)&rrb[h * DH];
#pragma unroll
    for (int u = 0; u < 4; u++) {
        int f = tid + 256 * u;
        int row = f >> 3, d8 = (f & 7) * 8;
        uint4 qv = *(const uint4*)&g_Qh[((size_t)(b * QL + i0 + row)) * EMB + h * DH + d8];
        const uint32_t* qw = (const uint32_t*)&qv;
#pragma unroll
        for (int j = 0; j < 4; j++) {
            float2 qf = f2_of_bf16x2(qw[j]);
            float2 bbv = bias2[(d8 >> 1) + j];
            sm[row * 36 + (d8 >> 1) + j] = bf16x2_of(qf.x + bbv.x, qf.y + bbv.y);
        }
    }
    CP_WAIT0();
    __syncthreads();

    const uint32_t aLd = sbase + (uint32_t)((wm * 16 + (lane & 15)) * 144 + (lane & 16));
    const uint32_t bLd = Rb + (uint32_t)((lane & 15) * 144 + (lane & 16));

    float s[8][4];
#pragma unroll
    for (int nf = 0; nf < 8; nf++)
#pragma unroll
        for (int e = 0; e < 4; e++) s[nf][e] = 0.f;

#pragma unroll
    for (int ks = 0; ks < 4; ks++) {
        uint32_t a0, a1, a2, a3;
        LDSM_X4(a0, a1, a2, a3, aLd + ks * 32);
#pragma unroll
        for (int nf2 = 0; nf2 < 4; nf2++) {
            uint32_t b0, b1, b2, b3;
            LDSM_X4(b0, b1, b2, b3, bLd + nf2 * 2304 + ks * 32);
            MMA16816(s[2 * nf2],     a0, a1, a2, a3, b0, b2);
            MMA16816(s[2 * nf2 + 1], a0, a1, a2, a3, b1, b3);
        }
    }

    bf16* bdb = g_BDh + (size_t)(b * NH + h) * QL * KLEN;
#pragma unroll
    for (int e = 0; e < 2; e++) {
        int i = i0 + wm * 16 + g + 8 * e;
#pragma unroll
        for (int nf = 0; nf < 8; nf++) {
            int p = p0 + nf * 8 + 2 * tig;
            int j0 = p - (QL - 1) + i;
            if (j0 >= 0)     bdb[(size_t)i * KLEN + j0]     = __float2bfloat16(s[nf][2 * e] * SCL2);
            if (j0 + 1 >= 0) bdb[(size_t)i * KLEN + j0 + 1] = __float2bfloat16(s[nf][2 * e + 1] * SCL2);
        }
    }
}

// ---------------- flash attention: split-KV streaming softmax ----------------
__global__ __launch_bounds__(256) void flash_mma(const float* __restrict__ rwb)
{
    extern __shared__ uint32_t smd[];
    const uint32_t sbase = smem_u32(smd);

    const int qt = 7 - (blockIdx.x >> 1), split = blockIdx.x & 1;
    const int h = blockIdx.y, b = blockIdx.z;
    const int qi0 = qt * 128;
    const int tid = threadIdx.x, lane = tid & 31, wm = tid >> 5;
    const int g = lane >> 2, tig = lane & 3;

    const int nkt = 2 * qt + 18;
    const int half = nkt >> 1;
    const int kt0 = split ? half : 0;
    const int kt1 = split ? nkt : half;

    const bf16* bdb = g_BDh + (size_t)(b * NH + h) * QL * KLEN + (size_t)qi0 * KLEN;

#define CPKV(kt, buf) do { \
        const int kj0_ = (kt) * 64; \
        uint32_t kb_ = sbase + 18432 + (uint32_t)(buf) * 36864; \
        _Pragma("unroll") for (int u = 0; u < 2; u++) { \
            int f_ = tid + 256 * u; \
            int row_ = f_ >> 3, c16_ = f_ & 7; \
            size_t go_ = ((size_t)(b * KLEN + kj0_ + row_)) * EMB + h * DH + c16_ * 8; \
            CPA16(kb_ + row_ * 144 + c16_ * 16, g_Kh + go_); \
            CPA16(kb_ + 9216 + row_ * 144 + c16_ * 16, g_Vh + go_); \
        } \
        _Pragma("unroll") for (int u = 0; u < 4; u++) { \
            int f_ = tid + 256 * u; \
            int row_ = f_ >> 3, c16_ = f_ & 7; \
            CPA16(kb_ + 18432 + row_ * 144 + c16_ * 16, \
                  bdb + (size_t)row_ * KLEN + kj0_ + c16_ * 8); \
        } \
        CP_COMMIT(); \
    } while (0)

    CPKV(kt0, kt0 & 1);
    const float2* bias2 = (const float2*)&rwb[h * DH];
#pragma unroll
    for (int u = 0; u < 4; u++) {
        int f = tid + 256 * u;
        int row = f >> 3, d8 = (f & 7) * 8;
        uint4 qv = *(const uint4*)&g_Qh[((size_t)(b * QL + qi0 + row)) * EMB + h * DH + d8];
        const uint32_t* qw = (const uint32_t*)&qv;
#pragma unroll
        for (int j = 0; j < 4; j++) {
            float2 qf = f2_of_bf16x2(qw[j]);
            float2 bbv = bias2[(d8 >> 1) + j];
            smd[row * 36 + (d8 >> 1) + j] =
                bf16x2_of((qf.x + bbv.x) * SCL2, (qf.y + bbv.y) * SCL2);
        }
    }

    float o[8][4];
#pragma unroll
    for (int nf = 0; nf < 8; nf++)
#pragma unroll
        for (int e = 0; e < 4; e++) o[nf][e] = 0.f;
    float lr[2] = {0.f, 0.f};

    const uint32_t qLd = sbase + (uint32_t)((wm * 16 + (lane & 15)) * 144 + (lane & 16));
    const uint32_t kLdOff = (uint32_t)((lane & 15) * 144 + (lane & 16));
    const uint32_t vLdOff = (uint32_t)(((lane & 7) + ((lane & 16) >> 1)) * 144 + (lane & 8) * 2);

    for (int kt = kt0; kt < kt1; kt++) {
        const int buf = kt & 1;
        if (kt + 1 < kt1) {
            CPKV(kt + 1, (kt + 1) & 1);
            CP_WAIT1();
        } else {
            CP_WAIT0();
        }
        __syncthreads();

        const uint32_t Kb = sbase + 18432 + (uint32_t)buf * 36864;
        const uint32_t kLd = Kb + kLdOff;
        const uint32_t vLd = Kb + 9216 + vLdOff;
        const int kj0 = kt * 64;
        const bool edge = (kt >= nkt - 2);

        // init S accumulators from BD (C-fragment layout == smem band layout)
        float s[8][4];
#pragma unroll
        for (int e = 0; e < 2; e++) {
            const int iloc = wm * 16 + g + 8 * e;
            const uint32_t* bdp = smd + 9216 * (buf + 1) + iloc * 36 + tig;
#pragma unroll
            for (int nf = 0; nf < 8; nf++) {
                float2 bd = f2_of_bf16x2(bdp[nf * 4]);
                s[nf][2 * e] = bd.x;
                s[nf][2 * e + 1] = bd.y;
            }
        }

        // S += Q @ K^T
#pragma unroll
        for (int ks = 0; ks < 4; ks++) {
            uint32_t a0, a1, a2, a3;
            LDSM_X4(a0, a1, a2, a3, qLd + ks * 32);
#pragma unroll
            for (int nf2 = 0; nf2 < 4; nf2++) {
                uint32_t b0, b1, b2, b3;
                LDSM_X4(b0, b1, b2, b3, kLd + nf2 * 2304 + ks * 32);
                MMA16816(s[2 * nf2],     a0, a1, a2, a3, b0, b2);
                MMA16816(s[2 * nf2 + 1], a0, a1, a2, a3, b1, b3);
            }
        }

        // mask (edge tiles only)
        if (edge) {
#pragma unroll
            for (int e = 0; e < 2; e++) {
                const int i = qi0 + wm * 16 + g + 8 * e;
                const int jb = kj0 + 2 * tig;
                const int jlim = i + ML;
#pragma unroll
                for (int nf = 0; nf < 8; nf++) {
                    int j0 = jb + nf * 8;
                    if (j0 > jlim)     s[nf][2 * e]     = -1e30f;
                    if (j0 + 1 > jlim) s[nf][2 * e + 1] = -1e30f;
                }
            }
        }

        // p = exp2(s); accumulate row sums (two independent chains)
#pragma unroll
        for (int e = 0; e < 2; e++) {
            float psA = 0.f, psB = 0.f;
#pragma unroll
            for (int nf = 0; nf < 4; nf++) {
                float p0 = ex2f(s[nf][2 * e]);
                float p1 = ex2f(s[nf][2 * e + 1]);
                s[nf][2 * e] = p0;
                s[nf][2 * e + 1] = p1;
                psA += p0 + p1;
            }
#pragma unroll
            for (int nf = 4; nf < 8; nf++) {
                float p0 = ex2f(s[nf][2 * e]);
                float p1 = ex2f(s[nf][2 * e + 1]);
                s[nf][2 * e] = p0;
                s[nf][2 * e + 1] = p1;
                psB += p0 + p1;
            }
            lr[e] += psA + psB;
        }

        // pack P fragments (C-layout == A-layout)
        uint32_t pa[4][4];
#pragma unroll
        for (int t = 0; t < 4; t++) {
            pa[t][0] = bf16x2_of(s[2 * t][0], s[2 * t][1]);
            pa[t][1] = bf16x2_of(s[2 * t][2], s[2 * t][3]);
            pa[t][2] = bf16x2_of(s[2 * t + 1][0], s[2 * t + 1][1]);
            pa[t][3] = bf16x2_of(s[2 * t + 1][2], s[2 * t + 1][3]);
        }

        // O += P @ V (V^T via ldmatrix.trans)
#pragma unroll
        for (int t = 0; t < 4; t++) {
#pragma unroll
            for (int nf2 = 0; nf2 < 4; nf2++) {
                uint32_t b0, b1, b2, b3;
                LDSM_X4_T(b0, b1, b2, b3, vLd + t * 2304 + nf2 * 32);
                MMA16816(o[2 * nf2],     pa[t][0], pa[t][1], pa[t][2], pa[t][3], b0, b2);
                MMA16816(o[2 * nf2 + 1], pa[t][0], pa[t][1], pa[t][2], pa[t][3], b1, b3);
            }
        }
        __syncthreads();
    }

    // store unnormalized partials
    float* AOp = g_AOp[split];
    float* Lp = g_Lp[split];
#pragma unroll
    for (int e = 0; e < 2; e++) {
        float ps = lr[e];
        ps += __shfl_xor_sync(0xffffffff, ps, 1);
        ps += __shfl_xor_sync(0xffffffff, ps, 2);
        int i = qi0 + wm * 16 + g + 8 * e;
        if (tig == 0)
            Lp[((size_t)b * NH + h) * QL + i] = ps;
#pragma unroll
        for (int nf = 0; nf < 8; nf++) {
            float2 v = make_float2(o[nf][2 * e], o[nf][2 * e + 1]);
            *(float2*)&AOp[((size_t)b * QL + i) * EMB + h * DH + nf * 8 + 2 * tig] = v;
        }
    }
}

// ---------------- layernorm ----------------
__global__ __launch_bounds__(256) void ln_kernel(
    const float* __restrict__ gamma, const float* __restrict__ beta,
    float* __restrict__ out)
{
    const int row = blockIdx.x;
    const int tid = threadIdx.x;
    const float* x = g_X + (size_t)row * EMB;
    float4 v = ((const float4*)x)[tid];
    float s = v.x + v.y + v.z + v.w;
    float s2 = v.x * v.x + v.y * v.y + v.z * v.z + v.w * v.w;
#pragma unroll
    for (int w = 1; w < 32; w <<= 1) {
        s += __shfl_xor_sync(0xffffffff, s, w);
        s2 += __shfl_xor_sync(0xffffffff, s2, w);
    }
    __shared__ float sh[16];
    __shared__ float red[2];
    int wid = tid >> 5, lid = tid & 31;
    if (lid == 0) { sh[wid] = s; sh[wid + 8] = s2; }
    __syncthreads();
    if (tid == 0) {
        float ts = 0.f, ts2 = 0.f;
#pragma unroll
        for (int i = 0; i < 8; i++) { ts += sh[i]; ts2 += sh[i + 8]; }
        red[0] = ts; red[1] = ts2;
    }
    __syncthreads();
    float mean = red[0] * (1.0f / EMB);
    float var = red[1] * (1.0f / EMB) - mean * mean;
    float rs = rsqrtf(var + 1e-3f);
    float4 gg = ((const float4*)gamma)[tid];
    float4 bt = ((const float4*)beta)[tid];
    float4 ov;
    ov.x = (v.x - mean) * rs * gg.x + bt.x;
    ov.y = (v.y - mean) * rs * gg.y + bt.y;
    ov.z = (v.z - mean) * rs * gg.z + bt.z;
    ov.w = (v.w - mean) * rs * gg.w + bt.w;
    ((float4*)(out + (size_t)row * EMB))[tid] = ov;
}

// ---------------- launch ----------------
extern "C" void kernel_launch(void* const* d_in, const int* in_sizes, int n_in,
                              void* d_out, int out_size)
{
    const float* w      = (const float*)d_in[0];
    const float* r      = (const float*)d_in[1];
    const float* rwb    = (const float*)d_in[3];
    const float* rrb    = (const float*)d_in[4];
    const float* member = (const float*)d_in[5];
    const float* Wq     = (const float*)d_in[6];
    const float* Wk     = (const float*)d_in[7];
    const float* Wv     = (const float*)d_in[8];
    const float* Wr     = (const float*)d_in[9];
    const float* Wo     = (const float*)d_in[10];
    const float* gamma  = (const float*)d_in[11];
    const float* beta   = (const float*)d_in[12];
    float* out = (float*)d_out;

    dim3 blk(256);

    // 0) transpose + convert weights to bf16 [n][k]
    transposeW<<<dim3(32, 32, 5), blk>>>(Wq, Wk, Wv, Wr, Wo);

    // 1) ALL projections (Q, fused KV, R) in one launch: 768 tiles
    proj_gemm<<<768, blk>>>(w, member, r);

    // 2) BD with fused rel_shift (prescaled by SCL2)
    bd_mma<<<dim3(32, 8, 32), blk>>>(rrb);

    // 3) flash attention split-KV (grid 512, dyn smem 92160B)
    static const int FLASH_SMEM = 92160;
    cudaFuncSetAttribute(flash_mma, cudaFuncAttributeMaxDynamicSharedMemorySize, FLASH_SMEM);
    flash_mma<<<dim3(16, NH, BB), blk, FLASH_SMEM>>>(rwb);

    // 3b) inverse row sums for fused combine
    linv_kernel<<<128, blk>>>();

    // 4) output projection + fused combine + residual (fp32 out)
    wo_gemm<<<dim3(8, 16), blk>>>(w);

    // 5) layernorm
    ln_kernel<<<BB * QL, blk>>>(gamma, beta, out);
}

// round 14
// speedup vs baseline: 1.0938x; 1.0938x over previous
#include <cuda_runtime.h>
#include <cuda_bf16.h>
#include <cstdint>

#define BB 2
#define QL 1024
#define ML 1024
#define KLEN 2048
#define EMB 1024
#define NH 16
#define DH 64

typedef __nv_bfloat16 bf16;
typedef __nv_bfloat162 bf162;

// scale folded into Q and BD: (1/sqrt(1024)) * log2(e)
#define SCL2 (0.03125f * 1.4426950408889634f)

// ---------------- scratch (static device, allocation-free) ----------------
__device__ bf16 g_Qh[BB * QL * EMB];
__device__ bf16 g_Kh[BB * KLEN * EMB];
__device__ bf16 g_Vh[BB * KLEN * EMB];
__device__ bf16 g_Rh[KLEN * EMB];
__device__ bf16 g_BDh[(size_t)BB * NH * QL * KLEN];
__device__ float g_AOp[2][BB * QL * EMB];   // split-KV partial O (unnormalized)
__device__ float g_Lp[2][BB * NH * QL];     // split-KV partial row sums
__device__ bf16 g_AOb[BB * QL * EMB];       // combined + normalized AO (bf16)
__device__ float g_X[BB * QL * EMB];
__device__ bf16 g_WTb[5ull * 1024 * 1024];

__device__ __forceinline__ uint32_t smem_u32(const void* p) {
    uint32_t a;
    asm("{ .reg .u64 t; cvta.to.shared.u64 t, %1; cvt.u32.u64 %0, t; }" : "=r"(a) : "l"(p));
    return a;
}
__device__ __forceinline__ uint32_t bf16x2_of(float lo, float hi) {
    uint32_t o;
    asm("cvt.rn.bf16x2.f32 %0, %1, %2;" : "=r"(o) : "f"(hi), "f"(lo));
    return o;
}
__device__ __forceinline__ float2 f2_of_bf16x2(uint32_t w) {
    bf162 t = *reinterpret_cast<bf162*>(&w);
    return __bfloat1622float2(t);
}
__device__ __forceinline__ float ex2f(float x) {
    float y;
    asm("ex2.approx.f32 %0, %1;" : "=f"(y) : "f"(x));
    return y;
}
#define MMA16816(C, A0, A1, A2, A3, B0, B1) \
    asm volatile("mma.sync.aligned.m16n8k16.row.col.f32.bf16.bf16.f32 " \
        "{%0,%1,%2,%3}, {%4,%5,%6,%7}, {%8,%9}, {%0,%1,%2,%3};" \
        : "+f"((C)[0]), "+f"((C)[1]), "+f"((C)[2]), "+f"((C)[3]) \
        : "r"(A0), "r"(A1), "r"(A2), "r"(A3), "r"(B0), "r"(B1))
#define LDSM_X4(d0, d1, d2, d3, addr) \
    asm volatile("ldmatrix.sync.aligned.m8n8.x4.shared.b16 {%0,%1,%2,%3}, [%4];" \
        : "=r"(d0), "=r"(d1), "=r"(d2), "=r"(d3) : "r"(addr))
#define LDSM_X4_T(d0, d1, d2, d3, addr) \
    asm volatile("ldmatrix.sync.aligned.m8n8.x4.trans.shared.b16 {%0,%1,%2,%3}, [%4];" \
        : "=r"(d0), "=r"(d1), "=r"(d2), "=r"(d3) : "r"(addr))
#define CPA16(dst, src) \
    asm volatile("cp.async.cg.shared.global [%0], [%1], 16;" :: "r"(dst), "l"(src) : "memory")
#define CP_COMMIT() asm volatile("cp.async.commit_group;" ::: "memory")
#define CP_WAIT0()  asm volatile("cp.async.wait_group 0;" ::: "memory")
#define CP_WAIT1()  asm volatile("cp.async.wait_group 1;" ::: "memory")

// ---------------- weight transpose + bf16 convert ----------------
__global__ __launch_bounds__(256) void transposeW(
    const float* __restrict__ w0, const float* __restrict__ w1,
    const float* __restrict__ w2, const float* __restrict__ w3,
    const float* __restrict__ w4)
{
    __shared__ float t[32][33];
    const float* src;
    switch (blockIdx.z) {
        case 0: src = w0; break;
        case 1: src = w1; break;
        case 2: src = w2; break;
        case 3: src = w3; break;
        default: src = w4; break;
    }
    bf16* dst = g_WTb + ((size_t)blockIdx.z << 20);
    int tx = threadIdx.x & 31, ty = threadIdx.x >> 5;
    int x = blockIdx.x * 32 + tx;
    int y = blockIdx.y * 32 + ty;
#pragma unroll
    for (int j = 0; j < 32; j += 8)
        t[ty + j][tx] = src[(size_t)(y + j) * EMB + x];
    __syncthreads();
    x = blockIdx.y * 32 + tx;
    y = blockIdx.x * 32 + ty;
#pragma unroll
    for (int j = 0; j < 32; j += 8)
        dst[(size_t)(y + j) * EMB + x] = __float2bfloat16(t[tx][ty + j]);
}

// ================= shared GEMM body (128x128 tile, ldmatrix, cp.async) =================
// mode 0: A fp32 rows direct. mode 1: fp32 gather cat(member=A, w=A2).
// mode 3: A bf16 [m][k] (AB), loaded via cp.async like B.
template <bool OBF>
__device__ __forceinline__ void gemm_tile_body(
    const float* __restrict__ A, const float* __restrict__ A2,
    const bf16* __restrict__ AB,
    const bf16* __restrict__ WT,
    void* C0v, void* C1v, const float* __restrict__ resid,
    int mode, int m0, int n0, uint32_t* smw)
{
    const uint32_t sbase = smem_u32(smw);
    const int tid = threadIdx.x;
    const int lane = tid & 31, wid = tid >> 5;
    const int wm = wid >> 1, wn = wid & 1;
    const int g = lane >> 2, tig = lane & 3;

    // fp32 A path geometry
    const float* ap[4];
    uint32_t swA[4];
    // bf16 A path geometry (mode 3)
    const bf16* abp[2];
    uint32_t dstA[2];
    if (mode != 3) {
#pragma unroll
        for (int u = 0; u < 4; u++) {
            int f4 = tid + 256 * u;
            int rr = f4 >> 3, c4 = f4 & 7;
            int m = m0 + rr;
            const float* arow;
            if (mode == 0) {
                arow = A + (size_t)m * EMB;
            } else {
                int b = m >> 11, t = m & 2047;
                arow = (t < ML) ? (A + ((size_t)b * ML + t) * EMB)
                                : (A2 + ((size_t)b * QL + (t - ML)) * EMB);
            }
            ap[u] = arow + c4 * 4;
            swA[u] = (uint32_t)(rr * 20 + c4 * 2);
        }
    } else {
#pragma unroll
        for (int v = 0; v < 2; v++) {
            int f16 = tid + 256 * v;
            int rr = f16 >> 2, c16 = f16 & 3;
            abp[v] = AB + (size_t)(m0 + rr) * EMB + c16 * 8;
            dstA[v] = sbase + (uint32_t)(rr * 80 + c16 * 16);
        }
    }
    const bf16* bp[2];
    uint32_t dstB[2];
#pragma unroll
    for (int v = 0; v < 2; v++) {
        int f16 = tid + 256 * v;
        int rr = f16 >> 2, c16 = f16 & 3;
        bp[v] = WT + (size_t)(n0 + rr) * EMB + c16 * 8;
        dstB[v] = sbase + 10240 + (uint32_t)(rr * 80 + c16 * 16);
    }

    float4 ra[4];
#define LDGA(k0) do { \
        _Pragma("unroll") for (int u = 0; u < 4; u++) ra[u] = *(const float4*)(ap[u] + (k0)); \
    } while (0)
#define STSA(buf) do { \
        uint32_t* Aw_ = smw + (buf) * 5120; \
        _Pragma("unroll") for (int u = 0; u < 4; u++) { \
            Aw_[swA[u]]     = bf16x2_of(ra[u].x, ra[u].y); \
            Aw_[swA[u] + 1] = bf16x2_of(ra[u].z, ra[u].w); \
        } \
    } while (0)
#define CPB(buf, k0) do { \
        if (mode == 3) { \
            _Pragma("unroll") for (int v = 0; v < 2; v++) \
                CPA16(dstA[v] + (buf) * 20480, abp[v] + (k0)); \
        } \
        _Pragma("unroll") for (int v = 0; v < 2; v++) \
            CPA16(dstB[v] + (buf) * 20480, bp[v] + (k0)); \
        CP_COMMIT(); \
    } while (0)

    const uint32_t aLd = sbase + (uint32_t)((wm * 32 + (lane & 15)) * 80 + (lane & 16));
    const uint32_t bLd = sbase + 10240 + (uint32_t)((wn * 64 + (lane & 15)) * 80 + (lane & 16));

    float c[2][8][4];
#pragma unroll
    for (int mf = 0; mf < 2; mf++)
#pragma unroll
        for (int nf = 0; nf < 8; nf++)
#pragma unroll
            for (int e = 0; e < 4; e++) c[mf][nf][e] = 0.f;

    if (mode != 3) LDGA(0);
    CPB(0, 0);
    if (mode != 3) STSA(0);
    CP_WAIT0();
    __syncthreads();

    for (int it = 0; it < 32; it++) {
        if (it + 1 < 32) {
            if (mode != 3) LDGA((it + 1) * 32);
            CPB((it + 1) & 1, (it + 1) * 32);
        }
        const uint32_t bufB = (uint32_t)(it & 1) * 20480;
#pragma unroll
        for (int ks = 0; ks < 2; ks++) {
            uint32_t a0, a1, a2, a3, a4, a5, a6, a7;
            LDSM_X4(a0, a1, a2, a3, aLd + bufB + ks * 32);
            LDSM_X4(a4, a5, a6, a7, aLd + bufB + 1280 + ks * 32);
#pragma unroll
            for (int nf2 = 0; nf2 < 4; nf2++) {
                uint32_t b0, b1, b2, b3;
                LDSM_X4(b0, b1, b2, b3, bLd + bufB + nf2 * 1280 + ks * 32);
                MMA16816(c[0][2 * nf2],     a0, a1, a2, a3, b0, b2);
                MMA16816(c[0][2 * nf2 + 1], a0, a1, a2, a3, b1, b3);
                MMA16816(c[1][2 * nf2],     a4, a5, a6, a7, b0, b2);
                MMA16816(c[1][2 * nf2 + 1], a4, a5, a6, a7, b1, b3);
            }
        }
        if (mode != 3 && it + 1 < 32) STSA((it + 1) & 1);
        CP_WAIT0();
        __syncthreads();
    }

    if (OBF) {
        bf16* C = (bf16*)((n0 < 1024) ? C0v : C1v);
        int col0 = (n0 & 1023) + wn * 64;
#pragma unroll
        for (int mf = 0; mf < 2; mf++) {
            int r0 = m0 + wm * 32 + mf * 16 + g;
#pragma unroll
            for (int nf = 0; nf < 8; nf++) {
                int col = col0 + nf * 8 + tig * 2;
                *(uint32_t*)&C[(size_t)r0 * EMB + col] = bf16x2_of(c[mf][nf][0], c[mf][nf][1]);
                *(uint32_t*)&C[(size_t)(r0 + 8) * EMB + col] = bf16x2_of(c[mf][nf][2], c[mf][nf][3]);
            }
        }
    } else {
        float* C = (float*)C0v;
#pragma unroll
        for (int mf = 0; mf < 2; mf++) {
            int r0 = m0 + wm * 32 + mf * 16 + g;
#pragma unroll
            for (int nf = 0; nf < 8; nf++) {
                int col = n0 + wn * 64 + nf * 8 + tig * 2;
                float2 v0 = make_float2(c[mf][nf][0], c[mf][nf][1]);
                float2 v1 = make_float2(c[mf][nf][2], c[mf][nf][3]);
                if (resid) {
                    float2 a0 = *(const float2*)(resid + (size_t)r0 * EMB + col);
                    float2 a1 = *(const float2*)(resid + (size_t)(r0 + 8) * EMB + col);
                    v0.x += a0.x; v0.y += a0.y;
                    v1.x += a1.x; v1.y += a1.y;
                }
                *(float2*)(C + (size_t)r0 * EMB + col) = v0;
                *(float2*)(C + (size_t)(r0 + 8) * EMB + col) = v1;
            }
        }
    }
#undef LDGA
#undef STSA
#undef CPB
}

// ---------------- fused projection GEMM: Q + KV + R in one launch ----------------
__global__ __launch_bounds__(256, 2) void proj_gemm(
    const float* __restrict__ w, const float* __restrict__ member,
    const float* __restrict__ r)
{
    __shared__ uint32_t smw[10240];
    const int t = blockIdx.x;
    const float *A, *A2 = nullptr;
    const bf16* WT;
    void *C0, *C1 = nullptr;
    int mode, m0, n0;
    if (t < 128) {
        A = w; WT = g_WTb; C0 = g_Qh; mode = 0;
        m0 = (t >> 3) * 128; n0 = (t & 7) * 128;
    } else if (t < 640) {
        int u = t - 128;
        A = member; A2 = w; WT = g_WTb + (1u << 20); C0 = g_Kh; C1 = g_Vh; mode = 1;
        m0 = (u >> 4) * 128; n0 = (u & 15) * 128;
    } else {
        int u = t - 640;
        A = r; WT = g_WTb + (3u << 20); C0 = g_Rh; mode = 0;
        m0 = (u >> 3) * 128; n0 = (u & 7) * 128;
    }
    gemm_tile_body<true>(A, A2, nullptr, WT, C0, C1, nullptr, mode, m0, n0, smw);
}

// ---------------- Wo GEMM (bf16 A via cp.async) + residual (fp32 out) ----------------
__global__ __launch_bounds__(256, 2) void wo_gemm(const float* __restrict__ resid)
{
    __shared__ uint32_t smw[10240];
    const int m0 = blockIdx.y * 128, n0 = blockIdx.x * 128;
    gemm_tile_body<false>(nullptr, nullptr, g_AOb, g_WTb + (4u << 20), g_X, nullptr,
                          resid, 3, m0, n0, smw);
}

// ---------------- BD via bf16 mma (ldmatrix), pre-shifted band write (x SCL2) ----------------
__global__ __launch_bounds__(256, 2) void bd_mma(const float* __restrict__ rrb)
{
    const int pt = blockIdx.x, it = blockIdx.y, bh = blockIdx.z;
    const int i0 = it * 128, p0 = pt * 64;
    if (i0 + p0 < 833) return;
    const int b = bh >> 4, h = bh & 15;

    __shared__ uint32_t sm[6912];
    const uint32_t sbase = smem_u32(sm);
    const uint32_t Rb = sbase + 18432;
    const int tid = threadIdx.x, lane = tid & 31, wm = tid >> 5;
    const int g = lane >> 2, tig = lane & 3;

#pragma unroll
    for (int u = 0; u < 2; u++) {
        int f = tid + 256 * u;
        int row = f >> 3, c16 = f & 7;
        CPA16(Rb + row * 144 + c16 * 16,
              g_Rh + ((size_t)(p0 + row)) * EMB + h * DH + c16 * 8);
    }
    CP_COMMIT();

    const float2* bias2 = (const float2*)&rrb[h * DH];
#pragma unroll
    for (int u = 0; u < 4; u++) {
        int f = tid + 256 * u;
        int row = f >> 3, d8 = (f & 7) * 8;
        uint4 qv = *(const uint4*)&g_Qh[((size_t)(b * QL + i0 + row)) * EMB + h * DH + d8];
        const uint32_t* qw = (const uint32_t*)&qv;
#pragma unroll
        for (int j = 0; j < 4; j++) {
            float2 qf = f2_of_bf16x2(qw[j]);
            float2 bbv = bias2[(d8 >> 1) + j];
            sm[row * 36 + (d8 >> 1) + j] = bf16x2_of(qf.x + bbv.x, qf.y + bbv.y);
        }
    }
    CP_WAIT0();
    __syncthreads();

    const uint32_t aLd = sbase + (uint32_t)((wm * 16 + (lane & 15)) * 144 + (lane & 16));
    const uint32_t bLd = Rb + (uint32_t)((lane & 15) * 144 + (lane & 16));

    float s[8][4];
#pragma unroll
    for (int nf = 0; nf < 8; nf++)
#pragma unroll
        for (int e = 0; e < 4; e++) s[nf][e] = 0.f;

#pragma unroll
    for (int ks = 0; ks < 4; ks++) {
        uint32_t a0, a1, a2, a3;
        LDSM_X4(a0, a1, a2, a3, aLd + ks * 32);
#pragma unroll
        for (int nf2 = 0; nf2 < 4; nf2++) {
            uint32_t b0, b1, b2, b3;
            LDSM_X4(b0, b1, b2, b3, bLd + nf2 * 2304 + ks * 32);
            MMA16816(s[2 * nf2],     a0, a1, a2, a3, b0, b2);
            MMA16816(s[2 * nf2 + 1], a0, a1, a2, a3, b1, b3);
        }
    }

    bf16* bdb = g_BDh + (size_t)(b * NH + h) * QL * KLEN;
#pragma unroll
    for (int e = 0; e < 2; e++) {
        int i = i0 + wm * 16 + g + 8 * e;
#pragma unroll
        for (int nf = 0; nf < 8; nf++) {
            int p = p0 + nf * 8 + 2 * tig;
            int j0 = p - (QL - 1) + i;
            if (j0 >= 0)     bdb[(size_t)i * KLEN + j0]     = __float2bfloat16(s[nf][2 * e] * SCL2);
            if (j0 + 1 >= 0) bdb[(size_t)i * KLEN + j0 + 1] = __float2bfloat16(s[nf][2 * e + 1] * SCL2);
        }
    }
}

// ---------------- flash attention: split-KV streaming softmax ----------------
__global__ __launch_bounds__(256) void flash_mma(const float* __restrict__ rwb)
{
    extern __shared__ uint32_t smd[];
    const uint32_t sbase = smem_u32(smd);

    const int qt = 7 - (blockIdx.x >> 1), split = blockIdx.x & 1;
    const int h = blockIdx.y, b = blockIdx.z;
    const int qi0 = qt * 128;
    const int tid = threadIdx.x, lane = tid & 31, wm = tid >> 5;
    const int g = lane >> 2, tig = lane & 3;

    const int nkt = 2 * qt + 18;
    const int half = nkt >> 1;
    const int kt0 = split ? half : 0;
    const int kt1 = split ? nkt : half;

    const bf16* bdb = g_BDh + (size_t)(b * NH + h) * QL * KLEN + (size_t)qi0 * KLEN;

#define CPKV(kt, buf) do { \
        const int kj0_ = (kt) * 64; \
        uint32_t kb_ = sbase + 18432 + (uint32_t)(buf) * 36864; \
        _Pragma("unroll") for (int u = 0; u < 2; u++) { \
            int f_ = tid + 256 * u; \
            int row_ = f_ >> 3, c16_ = f_ & 7; \
            size_t go_ = ((size_t)(b * KLEN + kj0_ + row_)) * EMB + h * DH + c16_ * 8; \
            CPA16(kb_ + row_ * 144 + c16_ * 16, g_Kh + go_); \
            CPA16(kb_ + 9216 + row_ * 144 + c16_ * 16, g_Vh + go_); \
        } \
        _Pragma("unroll") for (int u = 0; u < 4; u++) { \
            int f_ = tid + 256 * u; \
            int row_ = f_ >> 3, c16_ = f_ & 7; \
            CPA16(kb_ + 18432 + row_ * 144 + c16_ * 16, \
                  bdb + (size_t)row_ * KLEN + kj0_ + c16_ * 8); \
        } \
        CP_COMMIT(); \
    } while (0)

    CPKV(kt0, kt0 & 1);
    const float2* bias2 = (const float2*)&rwb[h * DH];
#pragma unroll
    for (int u = 0; u < 4; u++) {
        int f = tid + 256 * u;
        int row = f >> 3, d8 = (f & 7) * 8;
        uint4 qv = *(const uint4*)&g_Qh[((size_t)(b * QL + qi0 + row)) * EMB + h * DH + d8];
        const uint32_t* qw = (const uint32_t*)&qv;
#pragma unroll
        for (int j = 0; j < 4; j++) {
            float2 qf = f2_of_bf16x2(qw[j]);
            float2 bbv = bias2[(d8 >> 1) + j];
            smd[row * 36 + (d8 >> 1) + j] =
                bf16x2_of((qf.x + bbv.x) * SCL2, (qf.y + bbv.y) * SCL2);
        }
    }

    float o[8][4];
#pragma unroll
    for (int nf = 0; nf < 8; nf++)
#pragma unroll
        for (int e = 0; e < 4; e++) o[nf][e] = 0.f;
    float lr[2] = {0.f, 0.f};

    const uint32_t qLd = sbase + (uint32_t)((wm * 16 + (lane & 15)) * 144 + (lane & 16));
    const uint32_t kLdOff = (uint32_t)((lane & 15) * 144 + (lane & 16));
    const uint32_t vLdOff = (uint32_t)(((lane & 7) + ((lane & 16) >> 1)) * 144 + (lane & 8) * 2);

    for (int kt = kt0; kt < kt1; kt++) {
        const int buf = kt & 1;
        if (kt + 1 < kt1) {
            CPKV(kt + 1, (kt + 1) & 1);
            CP_WAIT1();
        } else {
            CP_WAIT0();
        }
        __syncthreads();

        const uint32_t Kb = sbase + 18432 + (uint32_t)buf * 36864;
        const uint32_t kLd = Kb + kLdOff;
        const uint32_t vLd = Kb + 9216 + vLdOff;
        const int kj0 = kt * 64;
        const bool edge = (kt >= nkt - 2);

        // init S accumulators from BD (C-fragment layout == smem band layout)
        float s[8][4];
#pragma unroll
        for (int e = 0; e < 2; e++) {
            const int iloc = wm * 16 + g + 8 * e;
            const uint32_t* bdp = smd + 9216 * (buf + 1) + iloc * 36 + tig;
#pragma unroll
            for (int nf = 0; nf < 8; nf++) {
                float2 bd = f2_of_bf16x2(bdp[nf * 4]);
                s[nf][2 * e] = bd.x;
                s[nf][2 * e + 1] = bd.y;
            }
        }

        // S += Q @ K^T
#pragma unroll
        for (int ks = 0; ks < 4; ks++) {
            uint32_t a0, a1, a2, a3;
            LDSM_X4(a0, a1, a2, a3, qLd + ks * 32);
#pragma unroll
            for (int nf2 = 0; nf2 < 4; nf2++) {
                uint32_t b0, b1, b2, b3;
                LDSM_X4(b0, b1, b2, b3, kLd + nf2 * 2304 + ks * 32);
                MMA16816(s[2 * nf2],     a0, a1, a2, a3, b0, b2);
                MMA16816(s[2 * nf2 + 1], a0, a1, a2, a3, b1, b3);
            }
        }

        // mask (edge tiles only)
        if (edge) {
#pragma unroll
            for (int e = 0; e < 2; e++) {
                const int i = qi0 + wm * 16 + g + 8 * e;
                const int jb = kj0 + 2 * tig;
                const int jlim = i + ML;
#pragma unroll
                for (int nf = 0; nf < 8; nf++) {
                    int j0 = jb + nf * 8;
                    if (j0 > jlim)     s[nf][2 * e]     = -1e30f;
                    if (j0 + 1 > jlim) s[nf][2 * e + 1] = -1e30f;
                }
            }
        }

        // p = exp2(s); accumulate row sums (two independent chains)
#pragma unroll
        for (int e = 0; e < 2; e++) {
            float psA = 0.f, psB = 0.f;
#pragma unroll
            for (int nf = 0; nf < 4; nf++) {
                float p0 = ex2f(s[nf][2 * e]);
                float p1 = ex2f(s[nf][2 * e + 1]);
                s[nf][2 * e] = p0;
                s[nf][2 * e + 1] = p1;
                psA += p0 + p1;
            }
#pragma unroll
            for (int nf = 4; nf < 8; nf++) {
                float p0 = ex2f(s[nf][2 * e]);
                float p1 = ex2f(s[nf][2 * e + 1]);
                s[nf][2 * e] = p0;
                s[nf][2 * e + 1] = p1;
                psB += p0 + p1;
            }
            lr[e] += psA + psB;
        }

        // pack P fragments (C-layout == A-layout)
        uint32_t pa[4][4];
#pragma unroll
        for (int t = 0; t < 4; t++) {
            pa[t][0] = bf16x2_of(s[2 * t][0], s[2 * t][1]);
            pa[t][1] = bf16x2_of(s[2 * t][2], s[2 * t][3]);
            pa[t][2] = bf16x2_of(s[2 * t + 1][0], s[2 * t + 1][1]);
            pa[t][3] = bf16x2_of(s[2 * t + 1][2], s[2 * t + 1][3]);
        }

        // O += P @ V (V^T via ldmatrix.trans)
#pragma unroll
        for (int t = 0; t < 4; t++) {
#pragma unroll
            for (int nf2 = 0; nf2 < 4; nf2++) {
                uint32_t b0, b1, b2, b3;
                LDSM_X4_T(b0, b1, b2, b3, vLd + t * 2304 + nf2 * 32);
                MMA16816(o[2 * nf2],     pa[t][0], pa[t][1], pa[t][2], pa[t][3], b0, b2);
                MMA16816(o[2 * nf2 + 1], pa[t][0], pa[t][1], pa[t][2], pa[t][3], b1, b3);
            }
        }
        __syncthreads();
    }

    // store unnormalized partials
    float* AOp = g_AOp[split];
    float* Lp = g_Lp[split];
#pragma unroll
    for (int e = 0; e < 2; e++) {
        float ps = lr[e];
        ps += __shfl_xor_sync(0xffffffff, ps, 1);
        ps += __shfl_xor_sync(0xffffffff, ps, 2);
        int i = qi0 + wm * 16 + g + 8 * e;
        if (tig == 0)
            Lp[((size_t)b * NH + h) * QL + i] = ps;
#pragma unroll
        for (int nf = 0; nf < 8; nf++) {
            float2 v = make_float2(o[nf][2 * e], o[nf][2 * e + 1]);
            *(float2*)&AOp[((size_t)b * QL + i) * EMB + h * DH + nf * 8 + 2 * tig] = v;
        }
    }
}

// ---------------- combine split-KV partials -> bf16: AOb = (O0+O1)/(l0+l1) ----------------
__global__ __launch_bounds__(256) void combine_ao()
{
    const int row = blockIdx.x;            // b*QL + q
    const int tid = threadIdx.x;
    const int b = row >> 10, q = row & 1023;
    const int col = tid * 4;
    const int h = col >> 6;
    float l = g_Lp[0][((size_t)b * NH + h) * QL + q] +
              g_Lp[1][((size_t)b * NH + h) * QL + q];
    float inv = 1.0f / l;
    float4 v0 = *(const float4*)&g_AOp[0][(size_t)row * EMB + col];
    float4 v1 = *(const float4*)&g_AOp[1][(size_t)row * EMB + col];
    uint32_t lo = bf16x2_of((v0.x + v1.x) * inv, (v0.y + v1.y) * inv);
    uint32_t hi = bf16x2_of((v0.z + v1.z) * inv, (v0.w + v1.w) * inv);
    uint2 packed = make_uint2(lo, hi);
    *(uint2*)&g_AOb[(size_t)row * EMB + col] = packed;
}

// ---------------- layernorm ----------------
__global__ __launch_bounds__(256) void ln_kernel(
    const float* __restrict__ gamma, const float* __restrict__ beta,
    float* __restrict__ out)
{
    const int row = blockIdx.x;
    const int tid = threadIdx.x;
    const float* x = g_X + (size_t)row * EMB;
    float4 v = ((const float4*)x)[tid];
    float s = v.x + v.y + v.z + v.w;
    float s2 = v.x * v.x + v.y * v.y + v.z * v.z + v.w * v.w;
#pragma unroll
    for (int w = 1; w < 32; w <<= 1) {
        s += __shfl_xor_sync(0xffffffff, s, w);
        s2 += __shfl_xor_sync(0xffffffff, s2, w);
    }
    __shared__ float sh[16];
    __shared__ float red[2];
    int wid = tid >> 5, lid = tid & 31;
    if (lid == 0) { sh[wid] = s; sh[wid + 8] = s2; }
    __syncthreads();
    if (tid == 0) {
        float ts = 0.f, ts2 = 0.f;
#pragma unroll
        for (int i = 0; i < 8; i++) { ts += sh[i]; ts2 += sh[i + 8]; }
        red[0] = ts; red[1] = ts2;
    }
    __syncthreads();
    float mean = red[0] * (1.0f / EMB);
    float var = red[1] * (1.0f / EMB) - mean * mean;
    float rs = rsqrtf(var + 1e-3f);
    float4 gg = ((const float4*)gamma)[tid];
    float4 bt = ((const float4*)beta)[tid];
    float4 ov;
    ov.x = (v.x - mean) * rs * gg.x + bt.x;
    ov.y = (v.y - mean) * rs * gg.y + bt.y;
    ov.z = (v.z - mean) * rs * gg.z + bt.z;
    ov.w = (v.w - mean) * rs * gg.w + bt.w;
    ((float4*)(out + (size_t)row * EMB))[tid] = ov;
}

// ---------------- launch ----------------
extern "C" void kernel_launch(void* const* d_in, const int* in_sizes, int n_in,
                              void* d_out, int out_size)
{
    const float* w      = (const float*)d_in[0];
    const float* r      = (const float*)d_in[1];
    const float* rwb    = (const float*)d_in[3];
    const float* rrb    = (const float*)d_in[4];
    const float* member = (const float*)d_in[5];
    const float* Wq     = (const float*)d_in[6];
    const float* Wk     = (const float*)d_in[7];
    const float* Wv     = (const float*)d_in[8];
    const float* Wr     = (const float*)d_in[9];
    const float* Wo     = (const float*)d_in[10];
    const float* gamma  = (const float*)d_in[11];
    const float* beta   = (const float*)d_in[12];
    float* out = (float*)d_out;

    dim3 blk(256);

    // 0) transpose + convert weights to bf16 [n][k]
    transposeW<<<dim3(32, 32, 5), blk>>>(Wq, Wk, Wv, Wr, Wo);

    // 1) ALL projections (Q, fused KV, R) in one launch: 768 tiles
    proj_gemm<<<768, blk>>>(w, member, r);

    // 2) BD with fused rel_shift (prescaled by SCL2)
    bd_mma<<<dim3(32, 8, 32), blk>>>(rrb);

    // 3) flash attention split-KV (grid 512, dyn smem 92160B)
    static const int FLASH_SMEM = 92160;
    cudaFuncSetAttribute(flash_mma, cudaFuncAttributeMaxDynamicSharedMemorySize, FLASH_SMEM);
    flash_mma<<<dim3(16, NH, BB), blk, FLASH_SMEM>>>(rwb);

    // 3b) combine partials -> bf16 AO
    combine_ao<<<BB * QL, blk>>>();

    // 4) output projection (bf16 A via cp.async) + residual
    wo_gemm<<<dim3(8, 16), blk>>>(w);

    // 5) layernorm
    ln_kernel<<<BB * QL, blk>>>(gamma, beta, out);
}

// round 15
// speedup vs baseline: 1.1228x; 1.0265x over previous
#include <cuda_runtime.h>
#include <cuda_bf16.h>
#include <cstdint>

#define BB 2
#define QL 1024
#define ML 1024
#define KLEN 2048
#define EMB 1024
#define NH 16
#define DH 64

typedef __nv_bfloat16 bf16;
typedef __nv_bfloat162 bf162;

// scale folded into Q and BD: (1/sqrt(1024)) * log2(e)
#define SCL2 (0.03125f * 1.4426950408889634f)

// ---------------- scratch (static device, allocation-free) ----------------
__device__ bf16 g_cath[BB * KLEN * EMB];    // bf16 cat(member, w)
__device__ bf16 g_rh[KLEN * EMB];           // bf16 r
__device__ bf16 g_Qh[BB * QL * EMB];
__device__ bf16 g_Kh[BB * KLEN * EMB];
__device__ bf16 g_Vh[BB * KLEN * EMB];
__device__ bf16 g_Rh[KLEN * EMB];
__device__ bf16 g_BDh[(size_t)BB * NH * QL * KLEN];
__device__ float g_AOp[2][BB * QL * EMB];   // split-KV partial O (unnormalized)
__device__ float g_Lp[2][BB * NH * QL];     // split-KV partial row sums
__device__ bf16 g_AOb[BB * QL * EMB];       // combined + normalized AO (bf16)
__device__ float g_X[BB * QL * EMB];
__device__ bf16 g_WTb[5ull * 1024 * 1024];

__device__ __forceinline__ uint32_t smem_u32(const void* p) {
    uint32_t a;
    asm("{ .reg .u64 t; cvta.to.shared.u64 t, %1; cvt.u32.u64 %0, t; }" : "=r"(a) : "l"(p));
    return a;
}
__device__ __forceinline__ uint32_t bf16x2_of(float lo, float hi) {
    uint32_t o;
    asm("cvt.rn.bf16x2.f32 %0, %1, %2;" : "=r"(o) : "f"(hi), "f"(lo));
    return o;
}
__device__ __forceinline__ float2 f2_of_bf16x2(uint32_t w) {
    bf162 t = *reinterpret_cast<bf162*>(&w);
    return __bfloat1622float2(t);
}
__device__ __forceinline__ float ex2f(float x) {
    float y;
    asm("ex2.approx.f32 %0, %1;" : "=f"(y) : "f"(x));
    return y;
}
#define MMA16816(C, A0, A1, A2, A3, B0, B1) \
    asm volatile("mma.sync.aligned.m16n8k16.row.col.f32.bf16.bf16.f32 " \
        "{%0,%1,%2,%3}, {%4,%5,%6,%7}, {%8,%9}, {%0,%1,%2,%3};" \
        : "+f"((C)[0]), "+f"((C)[1]), "+f"((C)[2]), "+f"((C)[3]) \
        : "r"(A0), "r"(A1), "r"(A2), "r"(A3), "r"(B0), "r"(B1))
#define LDSM_X4(d0, d1, d2, d3, addr) \
    asm volatile("ldmatrix.sync.aligned.m8n8.x4.shared.b16 {%0,%1,%2,%3}, [%4];" \
        : "=r"(d0), "=r"(d1), "=r"(d2), "=r"(d3) : "r"(addr))
#define LDSM_X4_T(d0, d1, d2, d3, addr) \
    asm volatile("ldmatrix.sync.aligned.m8n8.x4.trans.shared.b16 {%0,%1,%2,%3}, [%4];" \
        : "=r"(d0), "=r"(d1), "=r"(d2), "=r"(d3) : "r"(addr))
#define CPA16(dst, src) \
    asm volatile("cp.async.cg.shared.global [%0], [%1], 16;" :: "r"(dst), "l"(src) : "memory")
#define CP_COMMIT() asm volatile("cp.async.commit_group;" ::: "memory")
#define CP_WAIT0()  asm volatile("cp.async.wait_group 0;" ::: "memory")
#define CP_WAIT1()  asm volatile("cp.async.wait_group 1;" ::: "memory")

// ---------------- prep: convert GEMM A-inputs to bf16 ----------------
// g_cath[b][t][e] = bf16(cat(member, w)); g_rh = bf16(r)
#define CAT4 (BB * KLEN * EMB / 4)
__global__ __launch_bounds__(256) void prep_bf16(
    const float* __restrict__ w, const float* __restrict__ member,
    const float* __restrict__ r)
{
    int i = blockIdx.x * 256 + threadIdx.x;
    if (i < CAT4) {
        int f = i * 4;
        int b = f >> 21;
        int t = (f >> 10) & 2047;
        int e = f & 1023;
        const float* src = (t < ML)
            ? (member + ((size_t)b * ML + t) * EMB + e)
            : (w + ((size_t)b * QL + (t - ML)) * EMB + e);
        float4 v = *(const float4*)src;
        uint2 p = make_uint2(bf16x2_of(v.x, v.y), bf16x2_of(v.z, v.w));
        *(uint2*)&g_cath[f] = p;
    } else {
        int f = (i - CAT4) * 4;
        float4 v = *(const float4*)(r + f);
        uint2 p = make_uint2(bf16x2_of(v.x, v.y), bf16x2_of(v.z, v.w));
        *(uint2*)&g_rh[f] = p;
    }
}

// ---------------- weight transpose + bf16 convert ----------------
__global__ __launch_bounds__(256) void transposeW(
    const float* __restrict__ w0, const float* __restrict__ w1,
    const float* __restrict__ w2, const float* __restrict__ w3,
    const float* __restrict__ w4)
{
    __shared__ float t[32][33];
    const float* src;
    switch (blockIdx.z) {
        case 0: src = w0; break;
        case 1: src = w1; break;
        case 2: src = w2; break;
        case 3: src = w3; break;
        default: src = w4; break;
    }
    bf16* dst = g_WTb + ((size_t)blockIdx.z << 20);
    int tx = threadIdx.x & 31, ty = threadIdx.x >> 5;
    int x = blockIdx.x * 32 + tx;
    int y = blockIdx.y * 32 + ty;
#pragma unroll
    for (int j = 0; j < 32; j += 8)
        t[ty + j][tx] = src[(size_t)(y + j) * EMB + x];
    __syncthreads();
    x = blockIdx.y * 32 + tx;
    y = blockIdx.x * 32 + ty;
#pragma unroll
    for (int j = 0; j < 32; j += 8)
        dst[(size_t)(y + j) * EMB + x] = __float2bfloat16(t[tx][ty + j]);
}

// ================= bf16 GEMM body: 128x128 tile, pure cp.async A+B =================
// Atile/Btile: bf16 row-major [128][1024] slices (tile row 0). Accumulates c.
__device__ __forceinline__ void gemm_accum(
    const bf16* __restrict__ Atile, const bf16* __restrict__ Btile,
    float c[2][8][4], uint32_t* smw)
{
    const uint32_t sbase = smem_u32(smw);
    const int tid = threadIdx.x;
    const int lane = tid & 31, wid = tid >> 5;
    const int wm = wid >> 1, wn = wid & 1;

    const bf16* apv[2];
    const bf16* bpv[2];
    uint32_t dstA[2], dstB[2];
#pragma unroll
    for (int v = 0; v < 2; v++) {
        int f16 = tid + 256 * v;
        int rr = f16 >> 2, c16 = f16 & 3;
        apv[v] = Atile + (size_t)rr * EMB + c16 * 8;
        bpv[v] = Btile + (size_t)rr * EMB + c16 * 8;
        dstA[v] = sbase + (uint32_t)(rr * 80 + c16 * 16);
        dstB[v] = sbase + 10240 + (uint32_t)(rr * 80 + c16 * 16);
    }

#define CPAB(buf, k0) do { \
        _Pragma("unroll") for (int v = 0; v < 2; v++) { \
            CPA16(dstA[v] + (buf) * 20480, apv[v] + (k0)); \
            CPA16(dstB[v] + (buf) * 20480, bpv[v] + (k0)); \
        } \
        CP_COMMIT(); \
    } while (0)

    const uint32_t aLd = sbase + (uint32_t)((wm * 32 + (lane & 15)) * 80 + (lane & 16));
    const uint32_t bLd = sbase + 10240 + (uint32_t)((wn * 64 + (lane & 15)) * 80 + (lane & 16));

    CPAB(0, 0);
    CP_WAIT0();
    __syncthreads();

    for (int it = 0; it < 32; it++) {
        if (it + 1 < 32) CPAB((it + 1) & 1, (it + 1) * 32);
        const uint32_t bufB = (uint32_t)(it & 1) * 20480;
#pragma unroll
        for (int ks = 0; ks < 2; ks++) {
            uint32_t a0, a1, a2, a3, a4, a5, a6, a7;
            LDSM_X4(a0, a1, a2, a3, aLd + bufB + ks * 32);
            LDSM_X4(a4, a5, a6, a7, aLd + bufB + 1280 + ks * 32);
#pragma unroll
            for (int nf2 = 0; nf2 < 4; nf2++) {
                uint32_t b0, b1, b2, b3;
                LDSM_X4(b0, b1, b2, b3, bLd + bufB + nf2 * 1280 + ks * 32);
                MMA16816(c[0][2 * nf2],     a0, a1, a2, a3, b0, b2);
                MMA16816(c[0][2 * nf2 + 1], a0, a1, a2, a3, b1, b3);
                MMA16816(c[1][2 * nf2],     a4, a5, a6, a7, b0, b2);
                MMA16816(c[1][2 * nf2 + 1], a4, a5, a6, a7, b1, b3);
            }
        }
        CP_WAIT0();
        __syncthreads();
    }
#undef CPAB
}

// ---------------- fused projection GEMM: Q + KV + R in one launch ----------------
// tiles: [0,128) Q; [128,640) KV (N=2048 -> K then V); [640,768) R.
__global__ __launch_bounds__(256, 2) void proj_gemm()
{
    __shared__ uint32_t smw[10240];
    const int t = blockIdx.x;
    const bf16 *Atile, *Btile;
    bf16* C;
    int m0, n0, col0;
    if (t < 128) {
        m0 = (t >> 3) * 128; n0 = (t & 7) * 128;
        int b = m0 >> 10;
        Atile = g_cath + ((size_t)(b * KLEN + ML + (m0 & 1023))) * EMB;
        Btile = g_WTb + (size_t)n0 * EMB;
        C = g_Qh; col0 = n0;
    } else if (t < 640) {
        int u = t - 128;
        m0 = (u >> 4) * 128; n0 = (u & 15) * 128;
        Atile = g_cath + (size_t)m0 * EMB;
        Btile = g_WTb + (1u << 20) + (size_t)n0 * EMB;
        C = (n0 < 1024) ? g_Kh : g_Vh; col0 = n0 & 1023;
    } else {
        int u = t - 640;
        m0 = (u >> 3) * 128; n0 = (u & 7) * 128;
        Atile = g_rh + (size_t)m0 * EMB;
        Btile = g_WTb + (3u << 20) + (size_t)n0 * EMB;
        C = g_Rh; col0 = n0;
    }

    float c[2][8][4];
#pragma unroll
    for (int mf = 0; mf < 2; mf++)
#pragma unroll
        for (int nf = 0; nf < 8; nf++)
#pragma unroll
            for (int e = 0; e < 4; e++) c[mf][nf][e] = 0.f;

    gemm_accum(Atile, Btile, c, smw);

    const int lane = threadIdx.x & 31, wid = threadIdx.x >> 5;
    const int wm = wid >> 1, wn = wid & 1;
    const int g = lane >> 2, tig = lane & 3;
#pragma unroll
    for (int mf = 0; mf < 2; mf++) {
        int r0 = m0 + wm * 32 + mf * 16 + g;
#pragma unroll
        for (int nf = 0; nf < 8; nf++) {
            int col = col0 + wn * 64 + nf * 8 + tig * 2;
            *(uint32_t*)&C[(size_t)r0 * EMB + col] = bf16x2_of(c[mf][nf][0], c[mf][nf][1]);
            *(uint32_t*)&C[(size_t)(r0 + 8) * EMB + col] = bf16x2_of(c[mf][nf][2], c[mf][nf][3]);
        }
    }
}

// ---------------- Wo GEMM (bf16 A via cp.async) + residual (fp32 out) ----------------
__global__ __launch_bounds__(256, 2) void wo_gemm(const float* __restrict__ resid)
{
    __shared__ uint32_t smw[10240];
    const int m0 = blockIdx.y * 128, n0 = blockIdx.x * 128;

    float c[2][8][4];
#pragma unroll
    for (int mf = 0; mf < 2; mf++)
#pragma unroll
        for (int nf = 0; nf < 8; nf++)
#pragma unroll
            for (int e = 0; e < 4; e++) c[mf][nf][e] = 0.f;

    gemm_accum(g_AOb + (size_t)m0 * EMB,
               g_WTb + (4u << 20) + (size_t)n0 * EMB, c, smw);

    const int lane = threadIdx.x & 31, wid = threadIdx.x >> 5;
    const int wm = wid >> 1, wn = wid & 1;
    const int g = lane >> 2, tig = lane & 3;
#pragma unroll
    for (int mf = 0; mf < 2; mf++) {
        int r0 = m0 + wm * 32 + mf * 16 + g;
#pragma unroll
        for (int nf = 0; nf < 8; nf++) {
            int col = n0 + wn * 64 + nf * 8 + tig * 2;
            float2 v0 = make_float2(c[mf][nf][0], c[mf][nf][1]);
            float2 v1 = make_float2(c[mf][nf][2], c[mf][nf][3]);
            float2 a0 = *(const float2*)(resid + (size_t)r0 * EMB + col);
            float2 a1 = *(const float2*)(resid + (size_t)(r0 + 8) * EMB + col);
            v0.x += a0.x; v0.y += a0.y;
            v1.x += a1.x; v1.y += a1.y;
            *(float2*)(g_X + (size_t)r0 * EMB + col) = v0;
            *(float2*)(g_X + (size_t)(r0 + 8) * EMB + col) = v1;
        }
    }
}

// ---------------- BD via bf16 mma (ldmatrix), pre-shifted band write (x SCL2) ----------------
__global__ __launch_bounds__(256, 2) void bd_mma(const float* __restrict__ rrb)
{
    const int pt = blockIdx.x, it = blockIdx.y, bh = blockIdx.z;
    const int i0 = it * 128, p0 = pt * 64;
    if (i0 + p0 < 833) return;
    const int b = bh >> 4, h = bh & 15;

    __shared__ uint32_t sm[6912];
    const uint32_t sbase = smem_u32(sm);
    const uint32_t Rb = sbase + 18432;
    const int tid = threadIdx.x, lane = tid & 31, wm = tid >> 5;
    const int g = lane >> 2, tig = lane & 3;

#pragma unroll
    for (int u = 0; u < 2; u++) {
        int f = tid + 256 * u;
        int row = f >> 3, c16 = f & 7;
        CPA16(Rb + row * 144 + c16 * 16,
              g_Rh + ((size_t)(p0 + row)) * EMB + h * DH + c16 * 8);
    }
    CP_COMMIT();

    const float2* bias2 = (const float2*)&rrb[h * DH];
#pragma unroll
    for (int u = 0; u < 4; u++) {
        int f = tid + 256 * u;
        int row = f >> 3, d8 = (f & 7) * 8;
        uint4 qv = *(const uint4*)&g_Qh[((size_t)(b * QL + i0 + row)) * EMB + h * DH + d8];
        const uint32_t* qw = (const uint32_t*)&qv;
#pragma unroll
        for (int j = 0; j < 4; j++) {
            float2 qf = f2_of_bf16x2(qw[j]);
            float2 bbv = bias2[(d8 >> 1) + j];
            sm[row * 36 + (d8 >> 1) + j] = bf16x2_of(qf.x + bbv.x, qf.y + bbv.y);
        }
    }
    CP_WAIT0();
    __syncthreads();

    const uint32_t aLd = sbase + (uint32_t)((wm * 16 + (lane & 15)) * 144 + (lane & 16));
    const uint32_t bLd = Rb + (uint32_t)((lane & 15) * 144 + (lane & 16));

    float s[8][4];
#pragma unroll
    for (int nf = 0; nf < 8; nf++)
#pragma unroll
        for (int e = 0; e < 4; e++) s[nf][e] = 0.f;

#pragma unroll
    for (int ks = 0; ks < 4; ks++) {
        uint32_t a0, a1, a2, a3;
        LDSM_X4(a0, a1, a2, a3, aLd + ks * 32);
#pragma unroll
        for (int nf2 = 0; nf2 < 4; nf2++) {
            uint32_t b0, b1, b2, b3;
            LDSM_X4(b0, b1, b2, b3, bLd + nf2 * 2304 + ks * 32);
            MMA16816(s[2 * nf2],     a0, a1, a2, a3, b0, b2);
            MMA16816(s[2 * nf2 + 1], a0, a1, a2, a3, b1, b3);
        }
    }

    bf16* bdb = g_BDh + (size_t)(b * NH + h) * QL * KLEN;
#pragma unroll
    for (int e = 0; e < 2; e++) {
        int i = i0 + wm * 16 + g + 8 * e;
#pragma unroll
        for (int nf = 0; nf < 8; nf++) {
            int p = p0 + nf * 8 + 2 * tig;
            int j0 = p - (QL - 1) + i;
            if (j0 >= 0)     bdb[(size_t)i * KLEN + j0]     = __float2bfloat16(s[nf][2 * e] * SCL2);
            if (j0 + 1 >= 0) bdb[(size_t)i * KLEN + j0 + 1] = __float2bfloat16(s[nf][2 * e + 1] * SCL2);
        }
    }
}

// ---------------- flash attention: split-KV streaming softmax ----------------
__global__ __launch_bounds__(256) void flash_mma(const float* __restrict__ rwb)
{
    extern __shared__ uint32_t smd[];
    const uint32_t sbase = smem_u32(smd);

    const int qt = 7 - (blockIdx.x >> 1), split = blockIdx.x & 1;
    const int h = blockIdx.y, b = blockIdx.z;
    const int qi0 = qt * 128;
    const int tid = threadIdx.x, lane = tid & 31, wm = tid >> 5;
    const int g = lane >> 2, tig = lane & 3;

    const int nkt = 2 * qt + 18;
    const int half = nkt >> 1;
    const int kt0 = split ? half : 0;
    const int kt1 = split ? nkt : half;

    const bf16* bdb = g_BDh + (size_t)(b * NH + h) * QL * KLEN + (size_t)qi0 * KLEN;

#define CPKV(kt, buf) do { \
        const int kj0_ = (kt) * 64; \
        uint32_t kb_ = sbase + 18432 + (uint32_t)(buf) * 36864; \
        _Pragma("unroll") for (int u = 0; u < 2; u++) { \
            int f_ = tid + 256 * u; \
            int row_ = f_ >> 3, c16_ = f_ & 7; \
            size_t go_ = ((size_t)(b * KLEN + kj0_ + row_)) * EMB + h * DH + c16_ * 8; \
            CPA16(kb_ + row_ * 144 + c16_ * 16, g_Kh + go_); \
            CPA16(kb_ + 9216 + row_ * 144 + c16_ * 16, g_Vh + go_); \
        } \
        _Pragma("unroll") for (int u = 0; u < 4; u++) { \
            int f_ = tid + 256 * u; \
            int row_ = f_ >> 3, c16_ = f_ & 7; \
            CPA16(kb_ + 18432 + row_ * 144 + c16_ * 16, \
                  bdb + (size_t)row_ * KLEN + kj0_ + c16_ * 8); \
        } \
        CP_COMMIT(); \
    } while (0)

    CPKV(kt0, kt0 & 1);
    const float2* bias2 = (const float2*)&rwb[h * DH];
#pragma unroll
    for (int u = 0; u < 4; u++) {
        int f = tid + 256 * u;
        int row = f >> 3, d8 = (f & 7) * 8;
        uint4 qv = *(const uint4*)&g_Qh[((size_t)(b * QL + qi0 + row)) * EMB + h * DH + d8];
        const uint32_t* qw = (const uint32_t*)&qv;
#pragma unroll
        for (int j = 0; j < 4; j++) {
            float2 qf = f2_of_bf16x2(qw[j]);
            float2 bbv = bias2[(d8 >> 1) + j];
            smd[row * 36 + (d8 >> 1) + j] =
                bf16x2_of((qf.x + bbv.x) * SCL2, (qf.y + bbv.y) * SCL2);
        }
    }

    float o[8][4];
#pragma unroll
    for (int nf = 0; nf < 8; nf++)
#pragma unroll
        for (int e = 0; e < 4; e++) o[nf][e] = 0.f;
    float lr[2] = {0.f, 0.f};

    const uint32_t qLd = sbase + (uint32_t)((wm * 16 + (lane & 15)) * 144 + (lane & 16));
    const uint32_t kLdOff = (uint32_t)((lane & 15) * 144 + (lane & 16));
    const uint32_t vLdOff = (uint32_t)(((lane & 7) + ((lane & 16) >> 1)) * 144 + (lane & 8) * 2);

    for (int kt = kt0; kt < kt1; kt++) {
        const int buf = kt & 1;
        if (kt + 1 < kt1) {
            CPKV(kt + 1, (kt + 1) & 1);
            CP_WAIT1();
        } else {
            CP_WAIT0();
        }
        __syncthreads();

        const uint32_t Kb = sbase + 18432 + (uint32_t)buf * 36864;
        const uint32_t kLd = Kb + kLdOff;
        const uint32_t vLd = Kb + 9216 + vLdOff;
        const int kj0 = kt * 64;
        const bool edge = (kt >= nkt - 2);

        // init S accumulators from BD (C-fragment layout == smem band layout)
        float s[8][4];
#pragma unroll
        for (int e = 0; e < 2; e++) {
            const int iloc = wm * 16 + g + 8 * e;
            const uint32_t* bdp = smd + 9216 * (buf + 1) + iloc * 36 + tig;
#pragma unroll
            for (int nf = 0; nf < 8; nf++) {
                float2 bd = f2_of_bf16x2(bdp[nf * 4]);
                s[nf][2 * e] = bd.x;
                s[nf][2 * e + 1] = bd.y;
            }
        }

        // S += Q @ K^T
#pragma unroll
        for (int ks = 0; ks < 4; ks++) {
            uint32_t a0, a1, a2, a3;
            LDSM_X4(a0, a1, a2, a3, qLd + ks * 32);
#pragma unroll
            for (int nf2 = 0; nf2 < 4; nf2++) {
                uint32_t b0, b1, b2, b3;
                LDSM_X4(b0, b1, b2, b3, kLd + nf2 * 2304 + ks * 32);
                MMA16816(s[2 * nf2],     a0, a1, a2, a3, b0, b2);
                MMA16816(s[2 * nf2 + 1], a0, a1, a2, a3, b1, b3);
            }
        }

        // mask (edge tiles only)
        if (edge) {
#pragma unroll
            for (int e = 0; e < 2; e++) {
                const int i = qi0 + wm * 16 + g + 8 * e;
                const int jb = kj0 + 2 * tig;
                const int jlim = i + ML;
#pragma unroll
                for (int nf = 0; nf < 8; nf++) {
                    int j0 = jb + nf * 8;
                    if (j0 > jlim)     s[nf][2 * e]     = -1e30f;
                    if (j0 + 1 > jlim) s[nf][2 * e + 1] = -1e30f;
                }
            }
        }

        // p = exp2(s); accumulate row sums (two independent chains)
#pragma unroll
        for (int e = 0; e < 2; e++) {
            float psA = 0.f, psB = 0.f;
#pragma unroll
            for (int nf = 0; nf < 4; nf++) {
                float p0 = ex2f(s[nf][2 * e]);
                float p1 = ex2f(s[nf][2 * e + 1]);
                s[nf][2 * e] = p0;
                s[nf][2 * e + 1] = p1;
                psA += p0 + p1;
            }
#pragma unroll
            for (int nf = 4; nf < 8; nf++) {
                float p0 = ex2f(s[nf][2 * e]);
                float p1 = ex2f(s[nf][2 * e + 1]);
                s[nf][2 * e] = p0;
                s[nf][2 * e + 1] = p1;
                psB += p0 + p1;
            }
            lr[e] += psA + psB;
        }

        // pack P fragments (C-layout == A-layout)
        uint32_t pa[4][4];
#pragma unroll
        for (int t = 0; t < 4; t++) {
            pa[t][0] = bf16x2_of(s[2 * t][0], s[2 * t][1]);
            pa[t][1] = bf16x2_of(s[2 * t][2], s[2 * t][3]);
            pa[t][2] = bf16x2_of(s[2 * t + 1][0], s[2 * t + 1][1]);
            pa[t][3] = bf16x2_of(s[2 * t + 1][2], s[2 * t + 1][3]);
        }

        // O += P @ V (V^T via ldmatrix.trans)
#pragma unroll
        for (int t = 0; t < 4; t++) {
#pragma unroll
            for (int nf2 = 0; nf2 < 4; nf2++) {
                uint32_t b0, b1, b2, b3;
                LDSM_X4_T(b0, b1, b2, b3, vLd + t * 2304 + nf2 * 32);
                MMA16816(o[2 * nf2],     pa[t][0], pa[t][1], pa[t][2], pa[t][3], b0, b2);
                MMA16816(o[2 * nf2 + 1], pa[t][0], pa[t][1], pa[t][2], pa[t][3], b1, b3);
            }
        }
        __syncthreads();
    }

    // store unnormalized partials
    float* AOp = g_AOp[split];
    float* Lp = g_Lp[split];
#pragma unroll
    for (int e = 0; e < 2; e++) {
        float ps = lr[e];
        ps += __shfl_xor_sync(0xffffffff, ps, 1);
        ps += __shfl_xor_sync(0xffffffff, ps, 2);
        int i = qi0 + wm * 16 + g + 8 * e;
        if (tig == 0)
            Lp[((size_t)b * NH + h) * QL + i] = ps;
#pragma unroll
        for (int nf = 0; nf < 8; nf++) {
            float2 v = make_float2(o[nf][2 * e], o[nf][2 * e + 1]);
            *(float2*)&AOp[((size_t)b * QL + i) * EMB + h * DH + nf * 8 + 2 * tig] = v;
        }
    }
}

// ---------------- combine split-KV partials -> bf16: AOb = (O0+O1)/(l0+l1) ----------------
__global__ __launch_bounds__(256) void combine_ao()
{
    const int row = blockIdx.x;            // b*QL + q
    const int tid = threadIdx.x;
    const int b = row >> 10, q = row & 1023;
    const int col = tid * 4;
    const int h = col >> 6;
    float l = g_Lp[0][((size_t)b * NH + h) * QL + q] +
              g_Lp[1][((size_t)b * NH + h) * QL + q];
    float inv = 1.0f / l;
    float4 v0 = *(const float4*)&g_AOp[0][(size_t)row * EMB + col];
    float4 v1 = *(const float4*)&g_AOp[1][(size_t)row * EMB + col];
    uint32_t lo = bf16x2_of((v0.x + v1.x) * inv, (v0.y + v1.y) * inv);
    uint32_t hi = bf16x2_of((v0.z + v1.z) * inv, (v0.w + v1.w) * inv);
    uint2 packed = make_uint2(lo, hi);
    *(uint2*)&g_AOb[(size_t)row * EMB + col] = packed;
}

// ---------------- layernorm ----------------
__global__ __launch_bounds__(256) void ln_kernel(
    const float* __restrict__ gamma, const float* __restrict__ beta,
    float* __restrict__ out)
{
    const int row = blockIdx.x;
    const int tid = threadIdx.x;
    const float* x = g_X + (size_t)row * EMB;
    float4 v = ((const float4*)x)[tid];
    float s = v.x + v.y + v.z + v.w;
    float s2 = v.x * v.x + v.y * v.y + v.z * v.z + v.w * v.w;
#pragma unroll
    for (int w = 1; w < 32; w <<= 1) {
        s += __shfl_xor_sync(0xffffffff, s, w);
        s2 += __shfl_xor_sync(0xffffffff, s2, w);
    }
    __shared__ float sh[16];
    __shared__ float red[2];
    int wid = tid >> 5, lid = tid & 31;
    if (lid == 0) { sh[wid] = s; sh[wid + 8] = s2; }
    __syncthreads();
    if (tid == 0) {
        float ts = 0.f, ts2 = 0.f;
#pragma unroll
        for (int i = 0; i < 8; i++) { ts += sh[i]; ts2 += sh[i + 8]; }
        red[0] = ts; red[1] = ts2;
    }
    __syncthreads();
    float mean = red[0] * (1.0f / EMB);
    float var = red[1] * (1.0f / EMB) - mean * mean;
    float rs = rsqrtf(var + 1e-3f);
    float4 gg = ((const float4*)gamma)[tid];
    float4 bt = ((const float4*)beta)[tid];
    float4 ov;
    ov.x = (v.x - mean) * rs * gg.x + bt.x;
    ov.y = (v.y - mean) * rs * gg.y + bt.y;
    ov.z = (v.z - mean) * rs * gg.z + bt.z;
    ov.w = (v.w - mean) * rs * gg.w + bt.w;
    ((float4*)(out + (size_t)row * EMB))[tid] = ov;
}

// ---------------- launch ----------------
extern "C" void kernel_launch(void* const* d_in, const int* in_sizes, int n_in,
                              void* d_out, int out_size)
{
    const float* w      = (const float*)d_in[0];
    const float* r      = (const float*)d_in[1];
    const float* rwb    = (const float*)d_in[3];
    const float* rrb    = (const float*)d_in[4];
    const float* member = (const float*)d_in[5];
    const float* Wq     = (const float*)d_in[6];
    const float* Wk     = (const float*)d_in[7];
    const float* Wv     = (const float*)d_in[8];
    const float* Wr     = (const float*)d_in[9];
    const float* Wo     = (const float*)d_in[10];
    const float* gamma  = (const float*)d_in[11];
    const float* beta   = (const float*)d_in[12];
    float* out = (float*)d_out;

    dim3 blk(256);

    // 0) prep bf16 A-inputs + transpose/convert weights
    prep_bf16<<<6144, blk>>>(w, member, r);
    transposeW<<<dim3(32, 32, 5), blk>>>(Wq, Wk, Wv, Wr, Wo);

    // 1) ALL projections (Q, fused KV, R) in one launch: 768 tiles, pure cp.async
    proj_gemm<<<768, blk>>>();

    // 2) BD with fused rel_shift (prescaled by SCL2)
    bd_mma<<<dim3(32, 8, 32), blk>>>(rrb);

    // 3) flash attention split-KV (grid 512, dyn smem 92160B)
    static const int FLASH_SMEM = 92160;
    cudaFuncSetAttribute(flash_mma, cudaFuncAttributeMaxDynamicSharedMemorySize, FLASH_SMEM);
    flash_mma<<<dim3(16, NH, BB), blk, FLASH_SMEM>>>(rwb);

    // 3b) combine partials -> bf16 AO
    combine_ao<<<BB * QL, blk>>>();

    // 4) output projection (bf16 A via cp.async) + residual
    wo_gemm<<<dim3(8, 16), blk>>>(w);

    // 5) layernorm
    ln_kernel<<<BB * QL, blk>>>(gamma, beta, out);
}

// round 16
// speedup vs baseline: 1.3312x; 1.1856x over previous
#include <cuda_runtime.h>
#include <cuda_bf16.h>
#include <cstdint>

#define BB 2
#define QL 1024
#define ML 1024
#define KLEN 2048
#define EMB 1024
#define NH 16
#define DH 64
#define BDP 2304   // BD row pitch (2048 + 256 zero pad)

typedef __nv_bfloat16 bf16;
typedef __nv_bfloat162 bf162;

// scale folded into Q and BD: (1/sqrt(1024)) * log2(e)
#define SCL2 (0.03125f * 1.4426950408889634f)

// ---------------- scratch (static device, allocation-free) ----------------
__device__ bf16 g_cath[BB * KLEN * EMB];    // bf16 cat(member, w)
__device__ bf16 g_rh[KLEN * EMB];           // bf16 r
__device__ bf16 g_Qh[BB * QL * EMB];
__device__ bf16 g_Kh[BB * KLEN * EMB];
__device__ bf16 g_Vh[BB * KLEN * EMB];
__device__ bf16 g_Rh[KLEN * EMB];
__device__ bf16 g_BDu[(size_t)BB * NH * QL * BDP]; // UNSHIFTED BD [i][p], zero-padded
__device__ float g_AOp[2][BB * QL * EMB];   // split-KV partial O (unnormalized)
__device__ float g_Lp[2][BB * NH * QL];     // split-KV partial row sums
__device__ bf16 g_AOb[BB * QL * EMB];       // combined + normalized AO (bf16)
__device__ float g_X[BB * QL * EMB];
__device__ bf16 g_WTb[5ull * 1024 * 1024];

__device__ __forceinline__ uint32_t smem_u32(const void* p) {
    uint32_t a;
    asm("{ .reg .u64 t; cvta.to.shared.u64 t, %1; cvt.u32.u64 %0, t; }" : "=r"(a) : "l"(p));
    return a;
}
__device__ __forceinline__ uint32_t bf16x2_of(float lo, float hi) {
    uint32_t o;
    asm("cvt.rn.bf16x2.f32 %0, %1, %2;" : "=r"(o) : "f"(hi), "f"(lo));
    return o;
}
__device__ __forceinline__ float2 f2_of_bf16x2(uint32_t w) {
    bf162 t = *reinterpret_cast<bf162*>(&w);
    return __bfloat1622float2(t);
}
__device__ __forceinline__ float ex2f(float x) {
    float y;
    asm("ex2.approx.f32 %0, %1;" : "=f"(y) : "f"(x));
    return y;
}
#define MMA16816(C, A0, A1, A2, A3, B0, B1) \
    asm volatile("mma.sync.aligned.m16n8k16.row.col.f32.bf16.bf16.f32 " \
        "{%0,%1,%2,%3}, {%4,%5,%6,%7}, {%8,%9}, {%0,%1,%2,%3};" \
        : "+f"((C)[0]), "+f"((C)[1]), "+f"((C)[2]), "+f"((C)[3]) \
        : "r"(A0), "r"(A1), "r"(A2), "r"(A3), "r"(B0), "r"(B1))
#define LDSM_X4(d0, d1, d2, d3, addr) \
    asm volatile("ldmatrix.sync.aligned.m8n8.x4.shared.b16 {%0,%1,%2,%3}, [%4];" \
        : "=r"(d0), "=r"(d1), "=r"(d2), "=r"(d3) : "r"(addr))
#define LDSM_X4_T(d0, d1, d2, d3, addr) \
    asm volatile("ldmatrix.sync.aligned.m8n8.x4.trans.shared.b16 {%0,%1,%2,%3}, [%4];" \
        : "=r"(d0), "=r"(d1), "=r"(d2), "=r"(d3) : "r"(addr))
#define CPA16(dst, src) \
    asm volatile("cp.async.cg.shared.global [%0], [%1], 16;" :: "r"(dst), "l"(src) : "memory")
#define CP_COMMIT() asm volatile("cp.async.commit_group;" ::: "memory")
#define CP_WAIT0()  asm volatile("cp.async.wait_group 0;" ::: "memory")
#define CP_WAIT1()  asm volatile("cp.async.wait_group 1;" ::: "memory")

// ---------------- prep: convert GEMM A-inputs to bf16 ----------------
#define CAT4 (BB * KLEN * EMB / 4)
__global__ __launch_bounds__(256) void prep_bf16(
    const float* __restrict__ w, const float* __restrict__ member,
    const float* __restrict__ r)
{
    int i = blockIdx.x * 256 + threadIdx.x;
    if (i < CAT4) {
        int f = i * 4;
        int b = f >> 21;
        int t = (f >> 10) & 2047;
        int e = f & 1023;
        const float* src = (t < ML)
            ? (member + ((size_t)b * ML + t) * EMB + e)
            : (w + ((size_t)b * QL + (t - ML)) * EMB + e);
        float4 v = *(const float4*)src;
        uint2 p = make_uint2(bf16x2_of(v.x, v.y), bf16x2_of(v.z, v.w));
        *(uint2*)&g_cath[f] = p;
    } else {
        int f = (i - CAT4) * 4;
        float4 v = *(const float4*)(r + f);
        uint2 p = make_uint2(bf16x2_of(v.x, v.y), bf16x2_of(v.z, v.w));
        *(uint2*)&g_rh[f] = p;
    }
}

// ---------------- weight transpose + bf16 convert ----------------
__global__ __launch_bounds__(256) void transposeW(
    const float* __restrict__ w0, const float* __restrict__ w1,
    const float* __restrict__ w2, const float* __restrict__ w3,
    const float* __restrict__ w4)
{
    __shared__ float t[32][33];
    const float* src;
    switch (blockIdx.z) {
        case 0: src = w0; break;
        case 1: src = w1; break;
        case 2: src = w2; break;
        case 3: src = w3; break;
        default: src = w4; break;
    }
    bf16* dst = g_WTb + ((size_t)blockIdx.z << 20);
    int tx = threadIdx.x & 31, ty = threadIdx.x >> 5;
    int x = blockIdx.x * 32 + tx;
    int y = blockIdx.y * 32 + ty;
#pragma unroll
    for (int j = 0; j < 32; j += 8)
        t[ty + j][tx] = src[(size_t)(y + j) * EMB + x];
    __syncthreads();
    x = blockIdx.y * 32 + tx;
    y = blockIdx.x * 32 + ty;
#pragma unroll
    for (int j = 0; j < 32; j += 8)
        dst[(size_t)(y + j) * EMB + x] = __float2bfloat16(t[tx][ty + j]);
}

// ================= bf16 GEMM body: 128x128 tile, pure cp.async A+B =================
__device__ __forceinline__ void gemm_accum(
    const bf16* __restrict__ Atile, const bf16* __restrict__ Btile,
    float c[2][8][4], uint32_t* smw)
{
    const uint32_t sbase = smem_u32(smw);
    const int tid = threadIdx.x;
    const int lane = tid & 31, wid = tid >> 5;
    const int wm = wid >> 1, wn = wid & 1;

    const bf16* apv[2];
    const bf16* bpv[2];
    uint32_t dstA[2], dstB[2];
#pragma unroll
    for (int v = 0; v < 2; v++) {
        int f16 = tid + 256 * v;
        int rr = f16 >> 2, c16 = f16 & 3;
        apv[v] = Atile + (size_t)rr * EMB + c16 * 8;
        bpv[v] = Btile + (size_t)rr * EMB + c16 * 8;
        dstA[v] = sbase + (uint32_t)(rr * 80 + c16 * 16);
        dstB[v] = sbase + 10240 + (uint32_t)(rr * 80 + c16 * 16);
    }

#define CPAB(buf, k0) do { \
        _Pragma("unroll") for (int v = 0; v < 2; v++) { \
            CPA16(dstA[v] + (buf) * 20480, apv[v] + (k0)); \
            CPA16(dstB[v] + (buf) * 20480, bpv[v] + (k0)); \
        } \
        CP_COMMIT(); \
    } while (0)

    const uint32_t aLd = sbase + (uint32_t)((wm * 32 + (lane & 15)) * 80 + (lane & 16));
    const uint32_t bLd = sbase + 10240 + (uint32_t)((wn * 64 + (lane & 15)) * 80 + (lane & 16));

    CPAB(0, 0);
    CP_WAIT0();
    __syncthreads();

    for (int it = 0; it < 32; it++) {
        if (it + 1 < 32) CPAB((it + 1) & 1, (it + 1) * 32);
        const uint32_t bufB = (uint32_t)(it & 1) * 20480;
#pragma unroll
        for (int ks = 0; ks < 2; ks++) {
            uint32_t a0, a1, a2, a3, a4, a5, a6, a7;
            LDSM_X4(a0, a1, a2, a3, aLd + bufB + ks * 32);
            LDSM_X4(a4, a5, a6, a7, aLd + bufB + 1280 + ks * 32);
#pragma unroll
            for (int nf2 = 0; nf2 < 4; nf2++) {
                uint32_t b0, b1, b2, b3;
                LDSM_X4(b0, b1, b2, b3, bLd + bufB + nf2 * 1280 + ks * 32);
                MMA16816(c[0][2 * nf2],     a0, a1, a2, a3, b0, b2);
                MMA16816(c[0][2 * nf2 + 1], a0, a1, a2, a3, b1, b3);
                MMA16816(c[1][2 * nf2],     a4, a5, a6, a7, b0, b2);
                MMA16816(c[1][2 * nf2 + 1], a4, a5, a6, a7, b1, b3);
            }
        }
        CP_WAIT0();
        __syncthreads();
    }
#undef CPAB
}

// ---------------- fused projection GEMM: Q + KV + R in one launch ----------------
__global__ __launch_bounds__(256, 2) void proj_gemm()
{
    __shared__ uint32_t smw[10240];
    const int t = blockIdx.x;
    const bf16 *Atile, *Btile;
    bf16* C;
    int m0, n0, col0;
    if (t < 128) {
        m0 = (t >> 3) * 128; n0 = (t & 7) * 128;
        int b = m0 >> 10;
        Atile = g_cath + ((size_t)(b * KLEN + ML + (m0 & 1023))) * EMB;
        Btile = g_WTb + (size_t)n0 * EMB;
        C = g_Qh; col0 = n0;
    } else if (t < 640) {
        int u = t - 128;
        m0 = (u >> 4) * 128; n0 = (u & 15) * 128;
        Atile = g_cath + (size_t)m0 * EMB;
        Btile = g_WTb + (1u << 20) + (size_t)n0 * EMB;
        C = (n0 < 1024) ? g_Kh : g_Vh; col0 = n0 & 1023;
    } else {
        int u = t - 640;
        m0 = (u >> 3) * 128; n0 = (u & 7) * 128;
        Atile = g_rh + (size_t)m0 * EMB;
        Btile = g_WTb + (3u << 20) + (size_t)n0 * EMB;
        C = g_Rh; col0 = n0;
    }

    float c[2][8][4];
#pragma unroll
    for (int mf = 0; mf < 2; mf++)
#pragma unroll
        for (int nf = 0; nf < 8; nf++)
#pragma unroll
            for (int e = 0; e < 4; e++) c[mf][nf][e] = 0.f;

    gemm_accum(Atile, Btile, c, smw);

    const int lane = threadIdx.x & 31, wid = threadIdx.x >> 5;
    const int wm = wid >> 1, wn = wid & 1;
    const int g = lane >> 2, tig = lane & 3;
#pragma unroll
    for (int mf = 0; mf < 2; mf++) {
        int r0 = m0 + wm * 32 + mf * 16 + g;
#pragma unroll
        for (int nf = 0; nf < 8; nf++) {
            int col = col0 + wn * 64 + nf * 8 + tig * 2;
            *(uint32_t*)&C[(size_t)r0 * EMB + col] = bf16x2_of(c[mf][nf][0], c[mf][nf][1]);
            *(uint32_t*)&C[(size_t)(r0 + 8) * EMB + col] = bf16x2_of(c[mf][nf][2], c[mf][nf][3]);
        }
    }
}

// ---------------- Wo GEMM (bf16 A via cp.async) + residual (fp32 out) ----------------
__global__ __launch_bounds__(256, 2) void wo_gemm(const float* __restrict__ resid)
{
    __shared__ uint32_t smw[10240];
    const int m0 = blockIdx.y * 128, n0 = blockIdx.x * 128;

    float c[2][8][4];
#pragma unroll
    for (int mf = 0; mf < 2; mf++)
#pragma unroll
        for (int nf = 0; nf < 8; nf++)
#pragma unroll
            for (int e = 0; e < 4; e++) c[mf][nf][e] = 0.f;

    gemm_accum(g_AOb + (size_t)m0 * EMB,
               g_WTb + (4u << 20) + (size_t)n0 * EMB, c, smw);

    const int lane = threadIdx.x & 31, wid = threadIdx.x >> 5;
    const int wm = wid >> 1, wn = wid & 1;
    const int g = lane >> 2, tig = lane & 3;
#pragma unroll
    for (int mf = 0; mf < 2; mf++) {
        int r0 = m0 + wm * 32 + mf * 16 + g;
#pragma unroll
        for (int nf = 0; nf < 8; nf++) {
            int col = n0 + wn * 64 + nf * 8 + tig * 2;
            float2 v0 = make_float2(c[mf][nf][0], c[mf][nf][1]);
            float2 v1 = make_float2(c[mf][nf][2], c[mf][nf][3]);
            float2 a0 = *(const float2*)(resid + (size_t)r0 * EMB + col);
            float2 a1 = *(const float2*)(resid + (size_t)(r0 + 8) * EMB + col);
            v0.x += a0.x; v0.y += a0.y;
            v1.x += a1.x; v1.y += a1.y;
            *(float2*)(g_X + (size_t)r0 * EMB + col) = v0;
            *(float2*)(g_X + (size_t)(r0 + 8) * EMB + col) = v1;
        }
    }
}

// ---------------- BD via bf16 mma, UNSHIFTED coalesced store (x SCL2) ----------------
__global__ __launch_bounds__(256, 2) void bd_mma(const float* __restrict__ rrb)
{
    const int pt = blockIdx.x, it = blockIdx.y, bh = blockIdx.z;
    const int i0 = it * 128, p0 = pt * 64;
    if (i0 + p0 < 833) return;   // tile entirely below band (never consumed)
    const int b = bh >> 4, h = bh & 15;

    __shared__ uint32_t sm[6912];
    const uint32_t sbase = smem_u32(sm);
    const uint32_t Rb = sbase + 18432;
    const int tid = threadIdx.x, lane = tid & 31, wm = tid >> 5;
    const int g = lane >> 2, tig = lane & 3;

#pragma unroll
    for (int u = 0; u < 2; u++) {
        int f = tid + 256 * u;
        int row = f >> 3, c16 = f & 7;
        CPA16(Rb + row * 144 + c16 * 16,
              g_Rh + ((size_t)(p0 + row)) * EMB + h * DH + c16 * 8);
    }
    CP_COMMIT();

    const float2* bias2 = (const float2*)&rrb[h * DH];
#pragma unroll
    for (int u = 0; u < 4; u++) {
        int f = tid + 256 * u;
        int row = f >> 3, d8 = (f & 7) * 8;
        uint4 qv = *(const uint4*)&g_Qh[((size_t)(b * QL + i0 + row)) * EMB + h * DH + d8];
        const uint32_t* qw = (const uint32_t*)&qv;
#pragma unroll
        for (int j = 0; j < 4; j++) {
            float2 qf = f2_of_bf16x2(qw[j]);
            float2 bbv = bias2[(d8 >> 1) + j];
            sm[row * 36 + (d8 >> 1) + j] = bf16x2_of(qf.x + bbv.x, qf.y + bbv.y);
        }
    }
    CP_WAIT0();
    __syncthreads();

    const uint32_t aLd = sbase + (uint32_t)((wm * 16 + (lane & 15)) * 144 + (lane & 16));
    const uint32_t bLd = Rb + (uint32_t)((lane & 15) * 144 + (lane & 16));

    float s[8][4];
#pragma unroll
    for (int nf = 0; nf < 8; nf++)
#pragma unroll
        for (int e = 0; e < 4; e++) s[nf][e] = 0.f;

#pragma unroll
    for (int ks = 0; ks < 4; ks++) {
        uint32_t a0, a1, a2, a3;
        LDSM_X4(a0, a1, a2, a3, aLd + ks * 32);
#pragma unroll
        for (int nf2 = 0; nf2 < 4; nf2++) {
            uint32_t b0, b1, b2, b3;
            LDSM_X4(b0, b1, b2, b3, bLd + nf2 * 2304 + ks * 32);
            MMA16816(s[2 * nf2],     a0, a1, a2, a3, b0, b2);
            MMA16816(s[2 * nf2 + 1], a0, a1, a2, a3, b1, b3);
        }
    }

    // coalesced unshifted store: BDu[i][p], p even -> packed u32, no guards
    bf16* bdb = g_BDu + (size_t)(b * NH + h) * QL * BDP;
#pragma unroll
    for (int e = 0; e < 2; e++) {
        int i = i0 + wm * 16 + g + 8 * e;
#pragma unroll
        for (int nf = 0; nf < 8; nf++) {
            int p = p0 + nf * 8 + 2 * tig;
            *(uint32_t*)&bdb[(size_t)i * BDP + p] =
                bf16x2_of(s[nf][2 * e] * SCL2, s[nf][2 * e + 1] * SCL2);
        }
    }
}

// ---------------- flash attention: split-KV streaming softmax, shifted BD read ----------------
// smem bytes: Q [0,18432); buf b at 18432 + b*38912: K 9216 | V 9216 | BD 20480 (128x80 bf16).
// total = 18432 + 2*38912 = 96256.
__global__ __launch_bounds__(256) void flash_mma(const float* __restrict__ rwb)
{
    extern __shared__ uint32_t smd[];
    const uint32_t sbase = smem_u32(smd);

    const int qt = 7 - (blockIdx.x >> 1), split = blockIdx.x & 1;
    const int h = blockIdx.y, b = blockIdx.z;
    const int qi0 = qt * 128;
    const int tid = threadIdx.x, lane = tid & 31, wm = tid >> 5;
    const int g = lane >> 2, tig = lane & 3;

    const int nkt = 2 * qt + 18;
    const int half = nkt >> 1;
    const int kt0 = split ? half : 0;
    const int kt1 = split ? nkt : half;

    // BD row prefetch geometry: 1280 chunks (128 rows x 10 x 16B), 5 per thread
    int rowA[5], cA[5];
    size_t rpA[5];
    uint32_t dA[5];
#pragma unroll
    for (int u = 0; u < 5; u++) {
        int f = tid + 256 * u;
        rowA[u] = f / 10;
        cA[u] = f - rowA[u] * 10;
        rpA[u] = ((size_t)((b * NH + h) * QL + qi0 + rowA[u])) * BDP + cA[u] * 8;
        dA[u] = (uint32_t)(18432 + rowA[u] * 160 + cA[u] * 16);
    }

#define CPKV(kt, buf) do { \
        const int kj0_ = (kt) * 64; \
        const int b0_ = kj0_ + 1023 - qi0; \
        uint32_t kb_ = sbase + 18432 + (uint32_t)(buf) * 38912; \
        _Pragma("unroll") for (int u = 0; u < 2; u++) { \
            int f_ = tid + 256 * u; \
            int row_ = f_ >> 3, c16_ = f_ & 7; \
            size_t go_ = ((size_t)(b * KLEN + kj0_ + row_)) * EMB + h * DH + c16_ * 8; \
            CPA16(kb_ + row_ * 144 + c16_ * 16, g_Kh + go_); \
            CPA16(kb_ + 9216 + row_ * 144 + c16_ * 16, g_Vh + go_); \
        } \
        _Pragma("unroll") for (int u = 0; u < 5; u++) { \
            CPA16(kb_ + dA[u], g_BDu + rpA[u] + ((b0_ - rowA[u]) & ~7)); \
        } \
        CP_COMMIT(); \
    } while (0)

    CPKV(kt0, kt0 & 1);
    const float2* bias2 = (const float2*)&rwb[h * DH];
#pragma unroll
    for (int u = 0; u < 4; u++) {
        int f = tid + 256 * u;
        int row = f >> 3, d8 = (f & 7) * 8;
        uint4 qv = *(const uint4*)&g_Qh[((size_t)(b * QL + qi0 + row)) * EMB + h * DH + d8];
        const uint32_t* qw = (const uint32_t*)&qv;
#pragma unroll
        for (int j = 0; j < 4; j++) {
            float2 qf = f2_of_bf16x2(qw[j]);
            float2 bbv = bias2[(d8 >> 1) + j];
            smd[row * 36 + (d8 >> 1) + j] =
                bf16x2_of((qf.x + bbv.x) * SCL2, (qf.y + bbv.y) * SCL2);
        }
    }

    float o[8][4];
#pragma unroll
    for (int nf = 0; nf < 8; nf++)
#pragma unroll
        for (int e = 0; e < 4; e++) o[nf][e] = 0.f;
    float lr[2] = {0.f, 0.f};

    const uint32_t qLd = sbase + (uint32_t)((wm * 16 + (lane & 15)) * 144 + (lane & 16));
    const uint32_t kLdOff = (uint32_t)((lane & 15) * 144 + (lane & 16));
    const uint32_t vLdOff = (uint32_t)(((lane & 7) + ((lane & 16) >> 1)) * 144 + (lane & 8) * 2);

    for (int kt = kt0; kt < kt1; kt++) {
        const int buf = kt & 1;
        if (kt + 1 < kt1) {
            CPKV(kt + 1, (kt + 1) & 1);
            CP_WAIT1();
        } else {
            CP_WAIT0();
        }
        __syncthreads();

        const uint32_t Kb = sbase + 18432 + (uint32_t)buf * 38912;
        const uint32_t kLd = Kb + kLdOff;
        const uint32_t vLd = Kb + 9216 + vLdOff;
        const int kj0 = kt * 64;
        const int b0 = kj0 + 1023 - qi0;
        const bool edge = (kt >= nkt - 2);

        // init S from shifted BD window (2xLDS + PRMT funnel, branchless)
        float s[8][4];
        const uint32_t bdRow = Kb + 18432;
#pragma unroll
        for (int e = 0; e < 2; e++) {
            const int r = wm * 16 + g + 8 * e;
            const int off = (b0 - r) & 7;
            const uint32_t base = bdRow + (uint32_t)r * 160 +
                                  (uint32_t)(((off + 2 * tig) & ~1) << 1);
            const uint32_t sel = (off & 1) ? 0x5432u : 0x3210u;
#pragma unroll
            for (int nf = 0; nf < 8; nf++) {
                uint32_t w0, w1, pr;
                asm volatile("ld.shared.b32 %0, [%1];" : "=r"(w0) : "r"(base + 16 * nf));
                asm volatile("ld.shared.b32 %0, [%1];" : "=r"(w1) : "r"(base + 16 * nf + 4));
                asm("prmt.b32 %0, %1, %2, %3;" : "=r"(pr) : "r"(w0), "r"(w1), "r"(sel));
                float2 bd = f2_of_bf16x2(pr);
                s[nf][2 * e] = bd.x;
                s[nf][2 * e + 1] = bd.y;
            }
        }

        // S += Q @ K^T
#pragma unroll
        for (int ks = 0; ks < 4; ks++) {
            uint32_t a0, a1, a2, a3;
            LDSM_X4(a0, a1, a2, a3, qLd + ks * 32);
#pragma unroll
            for (int nf2 = 0; nf2 < 4; nf2++) {
                uint32_t b0r, b1r, b2r, b3r;
                LDSM_X4(b0r, b1r, b2r, b3r, kLd + nf2 * 2304 + ks * 32);
                MMA16816(s[2 * nf2],     a0, a1, a2, a3, b0r, b2r);
                MMA16816(s[2 * nf2 + 1], a0, a1, a2, a3, b1r, b3r);
            }
        }

        // mask (edge tiles only)
        if (edge) {
#pragma unroll
            for (int e = 0; e < 2; e++) {
                const int i = qi0 + wm * 16 + g + 8 * e;
                const int jb = kj0 + 2 * tig;
                const int jlim = i + ML;
#pragma unroll
                for (int nf = 0; nf < 8; nf++) {
                    int j0 = jb + nf * 8;
                    if (j0 > jlim)     s[nf][2 * e]     = -1e30f;
                    if (j0 + 1 > jlim) s[nf][2 * e + 1] = -1e30f;
                }
            }
        }

        // p = exp2(s); accumulate row sums (two independent chains)
#pragma unroll
        for (int e = 0; e < 2; e++) {
            float psA = 0.f, psB = 0.f;
#pragma unroll
            for (int nf = 0; nf < 4; nf++) {
                float p0 = ex2f(s[nf][2 * e]);
                float p1 = ex2f(s[nf][2 * e + 1]);
                s[nf][2 * e] = p0;
                s[nf][2 * e + 1] = p1;
                psA += p0 + p1;
            }
#pragma unroll
            for (int nf = 4; nf < 8; nf++) {
                float p0 = ex2f(s[nf][2 * e]);
                float p1 = ex2f(s[nf][2 * e + 1]);
                s[nf][2 * e] = p0;
                s[nf][2 * e + 1] = p1;
                psB += p0 + p1;
            }
            lr[e] += psA + psB;
        }

        // pack P fragments (C-layout == A-layout)
        uint32_t pa[4][4];
#pragma unroll
        for (int t = 0; t < 4; t++) {
            pa[t][0] = bf16x2_of(s[2 * t][0], s[2 * t][1]);
            pa[t][1] = bf16x2_of(s[2 * t][2], s[2 * t][3]);
            pa[t][2] = bf16x2_of(s[2 * t + 1][0], s[2 * t + 1][1]);
            pa[t][3] = bf16x2_of(s[2 * t + 1][2], s[2 * t + 1][3]);
        }

        // O += P @ V (V^T via ldmatrix.trans)
#pragma unroll
        for (int t = 0; t < 4; t++) {
#pragma unroll
            for (int nf2 = 0; nf2 < 4; nf2++) {
                uint32_t b0r, b1r, b2r, b3r;
                LDSM_X4_T(b0r, b1r, b2r, b3r, vLd + t * 2304 + nf2 * 32);
                MMA16816(o[2 * nf2],     pa[t][0], pa[t][1], pa[t][2], pa[t][3], b0r, b2r);
                MMA16816(o[2 * nf2 + 1], pa[t][0], pa[t][1], pa[t][2], pa[t][3], b1r, b3r);
            }
        }
        __syncthreads();
    }

    // store unnormalized partials
    float* AOp = g_AOp[split];
    float* Lp = g_Lp[split];
#pragma unroll
    for (int e = 0; e < 2; e++) {
        float ps = lr[e];
        ps += __shfl_xor_sync(0xffffffff, ps, 1);
        ps += __shfl_xor_sync(0xffffffff, ps, 2);
        int i = qi0 + wm * 16 + g + 8 * e;
        if (tig == 0)
            Lp[((size_t)b * NH + h) * QL + i] = ps;
#pragma unroll
        for (int nf = 0; nf < 8; nf++) {
            float2 v = make_float2(o[nf][2 * e], o[nf][2 * e + 1]);
            *(float2*)&AOp[((size_t)b * QL + i) * EMB + h * DH + nf * 8 + 2 * tig] = v;
        }
    }
}

// ---------------- combine split-KV partials -> bf16 ----------------
__global__ __launch_bounds__(256) void combine_ao()
{
    const int row = blockIdx.x;
    const int tid = threadIdx.x;
    const int b = row >> 10, q = row & 1023;
    const int col = tid * 4;
    const int h = col >> 6;
    float l = g_Lp[0][((size_t)b * NH + h) * QL + q] +
              g_Lp[1][((size_t)b * NH + h) * QL + q];
    float inv = 1.0f / l;
    float4 v0 = *(const float4*)&g_AOp[0][(size_t)row * EMB + col];
    float4 v1 = *(const float4*)&g_AOp[1][(size_t)row * EMB + col];
    uint32_t lo = bf16x2_of((v0.x + v1.x) * inv, (v0.y + v1.y) * inv);
    uint32_t hi = bf16x2_of((v0.z + v1.z) * inv, (v0.w + v1.w) * inv);
    uint2 packed = make_uint2(lo, hi);
    *(uint2*)&g_AOb[(size_t)row * EMB + col] = packed;
}

// ---------------- layernorm ----------------
__global__ __launch_bounds__(256) void ln_kernel(
    const float* __restrict__ gamma, const float* __restrict__ beta,
    float* __restrict__ out)
{
    const int row = blockIdx.x;
    const int tid = threadIdx.x;
    const float* x = g_X + (size_t)row * EMB;
    float4 v = ((const float4*)x)[tid];
    float s = v.x + v.y + v.z + v.w;
    float s2 = v.x * v.x + v.y * v.y + v.z * v.z + v.w * v.w;
#pragma unroll
    for (int w = 1; w < 32; w <<= 1) {
        s += __shfl_xor_sync(0xffffffff, s, w);
        s2 += __shfl_xor_sync(0xffffffff, s2, w);
    }
    __shared__ float sh[16];
    __shared__ float red[2];
    int wid = tid >> 5, lid = tid & 31;
    if (lid == 0) { sh[wid] = s; sh[wid + 8] = s2; }
    __syncthreads();
    if (tid == 0) {
        float ts = 0.f, ts2 = 0.f;
#pragma unroll
        for (int i = 0; i < 8; i++) { ts += sh[i]; ts2 += sh[i + 8]; }
        red[0] = ts; red[1] = ts2;
    }
    __syncthreads();
    float mean = red[0] * (1.0f / EMB);
    float var = red[1] * (1.0f / EMB) - mean * mean;
    float rs = rsqrtf(var + 1e-3f);
    float4 gg = ((const float4*)gamma)[tid];
    float4 bt = ((const float4*)beta)[tid];
    float4 ov;
    ov.x = (v.x - mean) * rs * gg.x + bt.x;
    ov.y = (v.y - mean) * rs * gg.y + bt.y;
    ov.z = (v.z - mean) * rs * gg.z + bt.z;
    ov.w = (v.w - mean) * rs * gg.w + bt.w;
    ((float4*)(out + (size_t)row * EMB))[tid] = ov;
}

// ---------------- launch ----------------
extern "C" void kernel_launch(void* const* d_in, const int* in_sizes, int n_in,
                              void* d_out, int out_size)
{
    const float* w      = (const float*)d_in[0];
    const float* r      = (const float*)d_in[1];
    const float* rwb    = (const float*)d_in[3];
    const float* rrb    = (const float*)d_in[4];
    const float* member = (const float*)d_in[5];
    const float* Wq     = (const float*)d_in[6];
    const float* Wk     = (const float*)d_in[7];
    const float* Wv     = (const float*)d_in[8];
    const float* Wr     = (const float*)d_in[9];
    const float* Wo     = (const float*)d_in[10];
    const float* gamma  = (const float*)d_in[11];
    const float* beta   = (const float*)d_in[12];
    float* out = (float*)d_out;

    dim3 blk(256);

    // 0) prep bf16 A-inputs + transpose/convert weights
    prep_bf16<<<6144, blk>>>(w, member, r);
    transposeW<<<dim3(32, 32, 5), blk>>>(Wq, Wk, Wv, Wr, Wo);

    // 1) ALL projections (Q, fused KV, R) in one launch
    proj_gemm<<<768, blk>>>();

    // 2) BD unshifted (coalesced store, prescaled by SCL2)
    bd_mma<<<dim3(32, 8, 32), blk>>>(rrb);

    // 3) flash attention split-KV (grid 512, dyn smem 96256B)
    static const int FLASH_SMEM = 96256;
    cudaFuncSetAttribute(flash_mma, cudaFuncAttributeMaxDynamicSharedMemorySize, FLASH_SMEM);
    flash_mma<<<dim3(16, NH, BB), blk, FLASH_SMEM>>>(rwb);

    // 3b) combine partials -> bf16 AO
    combine_ao<<<BB * QL, blk>>>();

    // 4) output projection (bf16 A via cp.async) + residual
    wo_gemm<<<dim3(8, 16), blk>>>(w);

    // 5) layernorm
    ln_kernel<<<BB * QL, blk>>>(gamma, beta, out);
}

// round 17
// speedup vs baseline: 1.3762x; 1.0338x over previous
#include <cuda_runtime.h>
#include <cuda_bf16.h>
#include <cstdint>

#define BB 2
#define QL 1024
#define ML 1024
#define KLEN 2048
#define EMB 1024
#define NH 16
#define DH 64
#define BDP 2304   // BD row pitch (2048 + 256 zero pad)

typedef __nv_bfloat16 bf16;
typedef __nv_bfloat162 bf162;

// scale folded into Q and BD: (1/sqrt(1024)) * log2(e)
#define SCL2 (0.03125f * 1.4426950408889634f)

// ---------------- scratch (static device, allocation-free) ----------------
__device__ bf16 g_cath[BB * KLEN * EMB];    // bf16 cat(member, w)
__device__ bf16 g_rh[KLEN * EMB];           // bf16 r
__device__ bf16 g_Qh[BB * QL * EMB];
__device__ bf16 g_Kh[BB * KLEN * EMB];
__device__ bf16 g_Vh[BB * KLEN * EMB];
__device__ bf16 g_Rh[KLEN * EMB];
__device__ bf16 g_bbs[NH * KLEN];           // SCL2 * rrb_h . rr_p
__device__ bf16 g_BDu[(size_t)BB * NH * QL * BDP]; // UNSHIFTED BD [i][p], zero-padded
__device__ float g_AOp[2][BB * QL * EMB];   // split-KV partial O (unnormalized)
__device__ float g_Lp[2][BB * NH * QL];     // split-KV partial row sums
__device__ bf16 g_AOb[BB * QL * EMB];       // combined + normalized AO (bf16)
__device__ float g_X[BB * QL * EMB];
__device__ bf16 g_WTb[5ull * 1024 * 1024];

__device__ __forceinline__ uint32_t smem_u32(const void* p) {
    uint32_t a;
    asm("{ .reg .u64 t; cvta.to.shared.u64 t, %1; cvt.u32.u64 %0, t; }" : "=r"(a) : "l"(p));
    return a;
}
__device__ __forceinline__ uint32_t bf16x2_of(float lo, float hi) {
    uint32_t o;
    asm("cvt.rn.bf16x2.f32 %0, %1, %2;" : "=r"(o) : "f"(hi), "f"(lo));
    return o;
}
__device__ __forceinline__ float2 f2_of_bf16x2(uint32_t w) {
    bf162 t = *reinterpret_cast<bf162*>(&w);
    return __bfloat1622float2(t);
}
__device__ __forceinline__ float ex2f(float x) {
    float y;
    asm("ex2.approx.f32 %0, %1;" : "=f"(y) : "f"(x));
    return y;
}
#define MMA16816(C, A0, A1, A2, A3, B0, B1) \
    asm volatile("mma.sync.aligned.m16n8k16.row.col.f32.bf16.bf16.f32 " \
        "{%0,%1,%2,%3}, {%4,%5,%6,%7}, {%8,%9}, {%0,%1,%2,%3};" \
        : "+f"((C)[0]), "+f"((C)[1]), "+f"((C)[2]), "+f"((C)[3]) \
        : "r"(A0), "r"(A1), "r"(A2), "r"(A3), "r"(B0), "r"(B1))
#define LDSM_X4(d0, d1, d2, d3, addr) \
    asm volatile("ldmatrix.sync.aligned.m8n8.x4.shared.b16 {%0,%1,%2,%3}, [%4];" \
        : "=r"(d0), "=r"(d1), "=r"(d2), "=r"(d3) : "r"(addr))
#define LDSM_X4_T(d0, d1, d2, d3, addr) \
    asm volatile("ldmatrix.sync.aligned.m8n8.x4.trans.shared.b16 {%0,%1,%2,%3}, [%4];" \
        : "=r"(d0), "=r"(d1), "=r"(d2), "=r"(d3) : "r"(addr))
#define CPA16(dst, src) \
    asm volatile("cp.async.cg.shared.global [%0], [%1], 16;" :: "r"(dst), "l"(src) : "memory")
#define CP_COMMIT() asm volatile("cp.async.commit_group;" ::: "memory")
#define CP_WAIT0()  asm volatile("cp.async.wait_group 0;" ::: "memory")
#define CP_WAIT1()  asm volatile("cp.async.wait_group 1;" ::: "memory")

// ---------------- prep: convert GEMM A-inputs to bf16 ----------------
#define CAT4 (BB * KLEN * EMB / 4)
__global__ __launch_bounds__(256) void prep_bf16(
    const float* __restrict__ w, const float* __restrict__ member,
    const float* __restrict__ r)
{
    int i = blockIdx.x * 256 + threadIdx.x;
    if (i < CAT4) {
        int f = i * 4;
        int b = f >> 21;
        int t = (f >> 10) & 2047;
        int e = f & 1023;
        const float* src = (t < ML)
            ? (member + ((size_t)b * ML + t) * EMB + e)
            : (w + ((size_t)b * QL + (t - ML)) * EMB + e);
        float4 v = *(const float4*)src;
        uint2 p = make_uint2(bf16x2_of(v.x, v.y), bf16x2_of(v.z, v.w));
        *(uint2*)&g_cath[f] = p;
    } else {
        int f = (i - CAT4) * 4;
        float4 v = *(const float4*)(r + f);
        uint2 p = make_uint2(bf16x2_of(v.x, v.y), bf16x2_of(v.z, v.w));
        *(uint2*)&g_rh[f] = p;
    }
}

// ---------------- weight transpose + bf16 convert ----------------
__global__ __launch_bounds__(256) void transposeW(
    const float* __restrict__ w0, const float* __restrict__ w1,
    const float* __restrict__ w2, const float* __restrict__ w3,
    const float* __restrict__ w4)
{
    __shared__ float t[32][33];
    const float* src;
    switch (blockIdx.z) {
        case 0: src = w0; break;
        case 1: src = w1; break;
        case 2: src = w2; break;
        case 3: src = w3; break;
        default: src = w4; break;
    }
    bf16* dst = g_WTb + ((size_t)blockIdx.z << 20);
    int tx = threadIdx.x & 31, ty = threadIdx.x >> 5;
    int x = blockIdx.x * 32 + tx;
    int y = blockIdx.y * 32 + ty;
#pragma unroll
    for (int j = 0; j < 32; j += 8)
        t[ty + j][tx] = src[(size_t)(y + j) * EMB + x];
    __syncthreads();
    x = blockIdx.y * 32 + tx;
    y = blockIdx.x * 32 + ty;
#pragma unroll
    for (int j = 0; j < 32; j += 8)
        dst[(size_t)(y + j) * EMB + x] = __float2bfloat16(t[tx][ty + j]);
}

// ---------------- bbs: g_bbs[h][p] = SCL2 * dot(rrb_h, rr_p_h) ----------------
__global__ __launch_bounds__(256) void bbs_kernel(const float* __restrict__ rrb)
{
    int idx = blockIdx.x * 256 + threadIdx.x;   // 32768
    int h = idx >> 11, p = idx & 2047;
    const bf16* rrow = g_Rh + (size_t)p * EMB + h * DH;
    const float* bias = rrb + h * DH;
    float acc = 0.f;
#pragma unroll
    for (int c = 0; c < 8; c++) {
        uint4 rv = *(const uint4*)(rrow + c * 8);
        const uint32_t* rw = (const uint32_t*)&rv;
#pragma unroll
        for (int j = 0; j < 4; j++) {
            float2 rf = f2_of_bf16x2(rw[j]);
            acc += bias[c * 8 + 2 * j] * rf.x + bias[c * 8 + 2 * j + 1] * rf.y;
        }
    }
    g_bbs[h * KLEN + p] = __float2bfloat16(acc * SCL2);
}

// ================= bf16 GEMM body: 128x128 tile, pure cp.async A+B =================
__device__ __forceinline__ void gemm_accum(
    const bf16* __restrict__ Atile, const bf16* __restrict__ Btile,
    float c[2][8][4], uint32_t* smw)
{
    const uint32_t sbase = smem_u32(smw);
    const int tid = threadIdx.x;
    const int lane = tid & 31, wid = tid >> 5;
    const int wm = wid >> 1, wn = wid & 1;

    const bf16* apv[2];
    const bf16* bpv[2];
    uint32_t dstA[2], dstB[2];
#pragma unroll
    for (int v = 0; v < 2; v++) {
        int f16 = tid + 256 * v;
        int rr = f16 >> 2, c16 = f16 & 3;
        apv[v] = Atile + (size_t)rr * EMB + c16 * 8;
        bpv[v] = Btile + (size_t)rr * EMB + c16 * 8;
        dstA[v] = sbase + (uint32_t)(rr * 80 + c16 * 16);
        dstB[v] = sbase + 10240 + (uint32_t)(rr * 80 + c16 * 16);
    }

#define CPAB(buf, k0) do { \
        _Pragma("unroll") for (int v = 0; v < 2; v++) { \
            CPA16(dstA[v] + (buf) * 20480, apv[v] + (k0)); \
            CPA16(dstB[v] + (buf) * 20480, bpv[v] + (k0)); \
        } \
        CP_COMMIT(); \
    } while (0)

    const uint32_t aLd = sbase + (uint32_t)((wm * 32 + (lane & 15)) * 80 + (lane & 16));
    const uint32_t bLd = sbase + 10240 + (uint32_t)((wn * 64 + (lane & 15)) * 80 + (lane & 16));

    CPAB(0, 0);
    CP_WAIT0();
    __syncthreads();

    for (int it = 0; it < 32; it++) {
        if (it + 1 < 32) CPAB((it + 1) & 1, (it + 1) * 32);
        const uint32_t bufB = (uint32_t)(it & 1) * 20480;
#pragma unroll
        for (int ks = 0; ks < 2; ks++) {
            uint32_t a0, a1, a2, a3, a4, a5, a6, a7;
            LDSM_X4(a0, a1, a2, a3, aLd + bufB + ks * 32);
            LDSM_X4(a4, a5, a6, a7, aLd + bufB + 1280 + ks * 32);
#pragma unroll
            for (int nf2 = 0; nf2 < 4; nf2++) {
                uint32_t b0, b1, b2, b3;
                LDSM_X4(b0, b1, b2, b3, bLd + bufB + nf2 * 1280 + ks * 32);
                MMA16816(c[0][2 * nf2],     a0, a1, a2, a3, b0, b2);
                MMA16816(c[0][2 * nf2 + 1], a0, a1, a2, a3, b1, b3);
                MMA16816(c[1][2 * nf2],     a4, a5, a6, a7, b0, b2);
                MMA16816(c[1][2 * nf2 + 1], a4, a5, a6, a7, b1, b3);
            }
        }
        CP_WAIT0();
        __syncthreads();
    }
#undef CPAB
}

// ---------------- fused projection GEMM: Q + KV + R in one launch ----------------
__global__ __launch_bounds__(256, 2) void proj_gemm()
{
    __shared__ uint32_t smw[10240];
    const int t = blockIdx.x;
    const bf16 *Atile, *Btile;
    bf16* C;
    int m0, n0, col0;
    if (t < 128) {
        m0 = (t >> 3) * 128; n0 = (t & 7) * 128;
        int b = m0 >> 10;
        Atile = g_cath + ((size_t)(b * KLEN + ML + (m0 & 1023))) * EMB;
        Btile = g_WTb + (size_t)n0 * EMB;
        C = g_Qh; col0 = n0;
    } else if (t < 640) {
        int u = t - 128;
        m0 = (u >> 4) * 128; n0 = (u & 15) * 128;
        Atile = g_cath + (size_t)m0 * EMB;
        Btile = g_WTb + (1u << 20) + (size_t)n0 * EMB;
        C = (n0 < 1024) ? g_Kh : g_Vh; col0 = n0 & 1023;
    } else {
        int u = t - 640;
        m0 = (u >> 3) * 128; n0 = (u & 7) * 128;
        Atile = g_rh + (size_t)m0 * EMB;
        Btile = g_WTb + (3u << 20) + (size_t)n0 * EMB;
        C = g_Rh; col0 = n0;
    }

    float c[2][8][4];
#pragma unroll
    for (int mf = 0; mf < 2; mf++)
#pragma unroll
        for (int nf = 0; nf < 8; nf++)
#pragma unroll
            for (int e = 0; e < 4; e++) c[mf][nf][e] = 0.f;

    gemm_accum(Atile, Btile, c, smw);

    const int lane = threadIdx.x & 31, wid = threadIdx.x >> 5;
    const int wm = wid >> 1, wn = wid & 1;
    const int g = lane >> 2, tig = lane & 3;
#pragma unroll
    for (int mf = 0; mf < 2; mf++) {
        int r0 = m0 + wm * 32 + mf * 16 + g;
#pragma unroll
        for (int nf = 0; nf < 8; nf++) {
            int col = col0 + wn * 64 + nf * 8 + tig * 2;
            *(uint32_t*)&C[(size_t)r0 * EMB + col] = bf16x2_of(c[mf][nf][0], c[mf][nf][1]);
            *(uint32_t*)&C[(size_t)(r0 + 8) * EMB + col] = bf16x2_of(c[mf][nf][2], c[mf][nf][3]);
        }
    }
}

// ---------------- Wo GEMM (bf16 A via cp.async) + residual (fp32 out) ----------------
__global__ __launch_bounds__(256, 2) void wo_gemm(const float* __restrict__ resid)
{
    __shared__ uint32_t smw[10240];
    const int m0 = blockIdx.y * 128, n0 = blockIdx.x * 128;

    float c[2][8][4];
#pragma unroll
    for (int mf = 0; mf < 2; mf++)
#pragma unroll
        for (int nf = 0; nf < 8; nf++)
#pragma unroll
            for (int e = 0; e < 4; e++) c[mf][nf][e] = 0.f;

    gemm_accum(g_AOb + (size_t)m0 * EMB,
               g_WTb + (4u << 20) + (size_t)n0 * EMB, c, smw);

    const int lane = threadIdx.x & 31, wid = threadIdx.x >> 5;
    const int wm = wid >> 1, wn = wid & 1;
    const int g = lane >> 2, tig = lane & 3;
#pragma unroll
    for (int mf = 0; mf < 2; mf++) {
        int r0 = m0 + wm * 32 + mf * 16 + g;
#pragma unroll
        for (int nf = 0; nf < 8; nf++) {
            int col = n0 + wn * 64 + nf * 8 + tig * 2;
            float2 v0 = make_float2(c[mf][nf][0], c[mf][nf][1]);
            float2 v1 = make_float2(c[mf][nf][2], c[mf][nf][3]);
            float2 a0 = *(const float2*)(resid + (size_t)r0 * EMB + col);
            float2 a1 = *(const float2*)(resid + (size_t)(r0 + 8) * EMB + col);
            v0.x += a0.x; v0.y += a0.y;
            v1.x += a1.x; v1.y += a1.y;
            *(float2*)(g_X + (size_t)r0 * EMB + col) = v0;
            *(float2*)(g_X + (size_t)(r0 + 8) * EMB + col) = v1;
        }
    }
}

// ---------------- BD: 128x128 tile, bias-folded, coalesced staged epilogue ----------------
// grid (16, 8, 32): p0 = bx*128, i0 = by*128. BDu = (Q.R^T)*SCL2 + bbs.
__global__ __launch_bounds__(256, 2) void bd_mma()
{
    const int p0 = blockIdx.x * 128, i0 = blockIdx.y * 128;
    if (i0 + p0 < 769) return;   // tile entirely below band (never consumed)
    const int bh = blockIdx.z;
    const int b = bh >> 4, h = bh & 15;

    __shared__ uint32_t sm[9216];     // A 128x144B | B 128x144B; reused for staging
    __shared__ uint32_t bbw[64];      // bbs tile: 128 bf16
    const uint32_t sbase = smem_u32(sm);
    const uint32_t bbase = smem_u32(bbw);
    const int tid = threadIdx.x, lane = tid & 31, wm = tid >> 5;
    const int g = lane >> 2, tig = lane & 3;

    // cp.async A (Q rows, no bias) + B (R rows)
#pragma unroll
    for (int u = 0; u < 4; u++) {
        int f = tid + 256 * u;
        int row = f >> 3, c16 = f & 7;
        CPA16(sbase + row * 144 + c16 * 16,
              g_Qh + ((size_t)(b * QL + i0 + row)) * EMB + h * DH + c16 * 8);
        CPA16(sbase + 18432 + row * 144 + c16 * 16,
              g_Rh + ((size_t)(p0 + row)) * EMB + h * DH + c16 * 8);
    }
    if (tid < 16)
        CPA16(bbase + tid * 16, g_bbs + h * KLEN + p0 + tid * 8);
    CP_COMMIT();
    CP_WAIT0();
    __syncthreads();

    const uint32_t aLd = sbase + (uint32_t)((wm * 16 + (lane & 15)) * 144 + (lane & 16));
    const uint32_t bLd = sbase + 18432 + (uint32_t)((lane & 15) * 144 + (lane & 16));

    float s[16][4];
#pragma unroll
    for (int nf = 0; nf < 16; nf++)
#pragma unroll
        for (int e = 0; e < 4; e++) s[nf][e] = 0.f;

#pragma unroll
    for (int ks = 0; ks < 4; ks++) {
        uint32_t a0, a1, a2, a3;
        LDSM_X4(a0, a1, a2, a3, aLd + ks * 32);
#pragma unroll
        for (int nf2 = 0; nf2 < 8; nf2++) {
            uint32_t b0, b1, b2, b3;
            LDSM_X4(b0, b1, b2, b3, bLd + nf2 * 2304 + ks * 32);
            MMA16816(s[2 * nf2],     a0, a1, a2, a3, b0, b2);
            MMA16816(s[2 * nf2 + 1], a0, a1, a2, a3, b1, b3);
        }
    }
    __syncthreads();   // done reading A/B; reuse sm for staging

    // stage packed bf16x2 rows: pitch 68 u32 (272B, 16B-aligned)
#pragma unroll
    for (int e = 0; e < 2; e++) {
        int row = wm * 16 + g + 8 * e;
#pragma unroll
        for (int nf = 0; nf < 16; nf++) {
            float2 bb = f2_of_bf16x2(bbw[nf * 4 + tig]);
            sm[row * 68 + nf * 4 + tig] =
                bf16x2_of(s[nf][2 * e] * SCL2 + bb.x, s[nf][2 * e + 1] * SCL2 + bb.y);
        }
    }
    __syncthreads();

    // coalesced store: 128 rows x 16 uint4; 8 per thread
    bf16* bdb = g_BDu + (size_t)(b * NH + h) * QL * BDP + p0;
#pragma unroll
    for (int u = 0; u < 8; u++) {
        int cch = tid + 256 * u;
        int row = cch >> 4, six = cch & 15;
        uint4 v = *(const uint4*)&sm[row * 68 + six * 4];
        *(uint4*)&bdb[(size_t)(i0 + row) * BDP + six * 8] = v;
    }
}

// ---------------- flash attention: split-KV streaming softmax, shifted BD read ----------------
__global__ __launch_bounds__(256) void flash_mma(const float* __restrict__ rwb)
{
    extern __shared__ uint32_t smd[];
    const uint32_t sbase = smem_u32(smd);

    const int qt = 7 - (blockIdx.x >> 1), split = blockIdx.x & 1;
    const int h = blockIdx.y, b = blockIdx.z;
    const int qi0 = qt * 128;
    const int tid = threadIdx.x, lane = tid & 31, wm = tid >> 5;
    const int g = lane >> 2, tig = lane & 3;

    const int nkt = 2 * qt + 18;
    const int half = nkt >> 1;
    const int kt0 = split ? half : 0;
    const int kt1 = split ? nkt : half;

    int rowA[5], cA[5];
    size_t rpA[5];
    uint32_t dA[5];
#pragma unroll
    for (int u = 0; u < 5; u++) {
        int f = tid + 256 * u;
        rowA[u] = f / 10;
        cA[u] = f - rowA[u] * 10;
        rpA[u] = ((size_t)((b * NH + h) * QL + qi0 + rowA[u])) * BDP + cA[u] * 8;
        dA[u] = (uint32_t)(18432 + rowA[u] * 160 + cA[u] * 16);
    }

#define CPKV(kt, buf) do { \
        const int kj0_ = (kt) * 64; \
        const int b0_ = kj0_ + 1023 - qi0; \
        uint32_t kb_ = sbase + 18432 + (uint32_t)(buf) * 38912; \
        _Pragma("unroll") for (int u = 0; u < 2; u++) { \
            int f_ = tid + 256 * u; \
            int row_ = f_ >> 3, c16_ = f_ & 7; \
            size_t go_ = ((size_t)(b * KLEN + kj0_ + row_)) * EMB + h * DH + c16_ * 8; \
            CPA16(kb_ + row_ * 144 + c16_ * 16, g_Kh + go_); \
            CPA16(kb_ + 9216 + row_ * 144 + c16_ * 16, g_Vh + go_); \
        } \
        _Pragma("unroll") for (int u = 0; u < 5; u++) { \
            CPA16(kb_ + dA[u], g_BDu + rpA[u] + ((b0_ - rowA[u]) & ~7)); \
        } \
        CP_COMMIT(); \
    } while (0)

    CPKV(kt0, kt0 & 1);
    const float2* bias2 = (const float2*)&rwb[h * DH];
#pragma unroll
    for (int u = 0; u < 4; u++) {
        int f = tid + 256 * u;
        int row = f >> 3, d8 = (f & 7) * 8;
        uint4 qv = *(const uint4*)&g_Qh[((size_t)(b * QL + qi0 + row)) * EMB + h * DH + d8];
        const uint32_t* qw = (const uint32_t*)&qv;
#pragma unroll
        for (int j = 0; j < 4; j++) {
            float2 qf = f2_of_bf16x2(qw[j]);
            float2 bbv = bias2[(d8 >> 1) + j];
            smd[row * 36 + (d8 >> 1) + j] =
                bf16x2_of((qf.x + bbv.x) * SCL2, (qf.y + bbv.y) * SCL2);
        }
    }

    float o[8][4];
#pragma unroll
    for (int nf = 0; nf < 8; nf++)
#pragma unroll
        for (int e = 0; e < 4; e++) o[nf][e] = 0.f;
    float lr[2] = {0.f, 0.f};

    const uint32_t qLd = sbase + (uint32_t)((wm * 16 + (lane & 15)) * 144 + (lane & 16));
    const uint32_t kLdOff = (uint32_t)((lane & 15) * 144 + (lane & 16));
    const uint32_t vLdOff = (uint32_t)(((lane & 7) + ((lane & 16) >> 1)) * 144 + (lane & 8) * 2);

    for (int kt = kt0; kt < kt1; kt++) {
        const int buf = kt & 1;
        if (kt + 1 < kt1) {
            CPKV(kt + 1, (kt + 1) & 1);
            CP_WAIT1();
        } else {
            CP_WAIT0();
        }
        __syncthreads();

        const uint32_t Kb = sbase + 18432 + (uint32_t)buf * 38912;
        const uint32_t kLd = Kb + kLdOff;
        const uint32_t vLd = Kb + 9216 + vLdOff;
        const int kj0 = kt * 64;
        const int b0 = kj0 + 1023 - qi0;
        const bool edge = (kt >= nkt - 2);

        float s[8][4];
        const uint32_t bdRow = Kb + 18432;
#pragma unroll
        for (int e = 0; e < 2; e++) {
            const int r = wm * 16 + g + 8 * e;
            const int off = (b0 - r) & 7;
            const uint32_t base = bdRow + (uint32_t)r * 160 +
                                  (uint32_t)(((off + 2 * tig) & ~1) << 1);
            const uint32_t sel = (off & 1) ? 0x5432u : 0x3210u;
#pragma unroll
            for (int nf = 0; nf < 8; nf++) {
                uint32_t w0, w1, pr;
                asm volatile("ld.shared.b32 %0, [%1];" : "=r"(w0) : "r"(base + 16 * nf));
                asm volatile("ld.shared.b32 %0, [%1];" : "=r"(w1) : "r"(base + 16 * nf + 4));
                asm("prmt.b32 %0, %1, %2, %3;" : "=r"(pr) : "r"(w0), "r"(w1), "r"(sel));
                float2 bd = f2_of_bf16x2(pr);
                s[nf][2 * e] = bd.x;
                s[nf][2 * e + 1] = bd.y;
            }
        }

#pragma unroll
        for (int ks = 0; ks < 4; ks++) {
            uint32_t a0, a1, a2, a3;
            LDSM_X4(a0, a1, a2, a3, qLd + ks * 32);
#pragma unroll
            for (int nf2 = 0; nf2 < 4; nf2++) {
                uint32_t b0r, b1r, b2r, b3r;
                LDSM_X4(b0r, b1r, b2r, b3r, kLd + nf2 * 2304 + ks * 32);
                MMA16816(s[2 * nf2],     a0, a1, a2, a3, b0r, b2r);
                MMA16816(s[2 * nf2 + 1], a0, a1, a2, a3, b1r, b3r);
            }
        }

        if (edge) {
#pragma unroll
            for (int e = 0; e < 2; e++) {
                const int i = qi0 + wm * 16 + g + 8 * e;
                const int jb = kj0 + 2 * tig;
                const int jlim = i + ML;
#pragma unroll
                for (int nf = 0; nf < 8; nf++) {
                    int j0 = jb + nf * 8;
                    if (j0 > jlim)     s[nf][2 * e]     = -1e30f;
                    if (j0 + 1 > jlim) s[nf][2 * e + 1] = -1e30f;
                }
            }
        }

#pragma unroll
        for (int e = 0; e < 2; e++) {
            float psA = 0.f, psB = 0.f;
#pragma unroll
            for (int nf = 0; nf < 4; nf++) {
                float p0 = ex2f(s[nf][2 * e]);
                float p1 = ex2f(s[nf][2 * e + 1]);
                s[nf][2 * e] = p0;
                s[nf][2 * e + 1] = p1;
                psA += p0 + p1;
            }
#pragma unroll
            for (int nf = 4; nf < 8; nf++) {
                float p0 = ex2f(s[nf][2 * e]);
                float p1 = ex2f(s[nf][2 * e + 1]);
                s[nf][2 * e] = p0;
                s[nf][2 * e + 1] = p1;
                psB += p0 + p1;
            }
            lr[e] += psA + psB;
        }

        uint32_t pa[4][4];
#pragma unroll
        for (int t = 0; t < 4; t++) {
            pa[t][0] = bf16x2_of(s[2 * t][0], s[2 * t][1]);
            pa[t][1] = bf16x2_of(s[2 * t][2], s[2 * t][3]);
            pa[t][2] = bf16x2_of(s[2 * t + 1][0], s[2 * t + 1][1]);
            pa[t][3] = bf16x2_of(s[2 * t + 1][2], s[2 * t + 1][3]);
        }

#pragma unroll
        for (int t = 0; t < 4; t++) {
#pragma unroll
            for (int nf2 = 0; nf2 < 4; nf2++) {
                uint32_t b0r, b1r, b2r, b3r;
                LDSM_X4_T(b0r, b1r, b2r, b3r, vLd + t * 2304 + nf2 * 32);
                MMA16816(o[2 * nf2],     pa[t][0], pa[t][1], pa[t][2], pa[t][3], b0r, b2r);
                MMA16816(o[2 * nf2 + 1], pa[t][0], pa[t][1], pa[t][2], pa[t][3], b1r, b3r);
            }
        }
        __syncthreads();
    }

    float* AOp = g_AOp[split];
    float* Lp = g_Lp[split];
#pragma unroll
    for (int e = 0; e < 2; e++) {
        float ps = lr[e];
        ps += __shfl_xor_sync(0xffffffff, ps, 1);
        ps += __shfl_xor_sync(0xffffffff, ps, 2);
        int i = qi0 + wm * 16 + g + 8 * e;
        if (tig == 0)
            Lp[((size_t)b * NH + h) * QL + i] = ps;
#pragma unroll
        for (int nf = 0; nf < 8; nf++) {
            float2 v = make_float2(o[nf][2 * e], o[nf][2 * e + 1]);
            *(float2*)&AOp[((size_t)b * QL + i) * EMB + h * DH + nf * 8 + 2 * tig] = v;
        }
    }
}

// ---------------- combine split-KV partials -> bf16 ----------------
__global__ __launch_bounds__(256) void combine_ao()
{
    const int row = blockIdx.x;
    const int tid = threadIdx.x;
    const int b = row >> 10, q = row & 1023;
    const int col = tid * 4;
    const int h = col >> 6;
    float l = g_Lp[0][((size_t)b * NH + h) * QL + q] +
              g_Lp[1][((size_t)b * NH + h) * QL + q];
    float inv = 1.0f / l;
    float4 v0 = *(const float4*)&g_AOp[0][(size_t)row * EMB + col];
    float4 v1 = *(const float4*)&g_AOp[1][(size_t)row * EMB + col];
    uint32_t lo = bf16x2_of((v0.x + v1.x) * inv, (v0.y + v1.y) * inv);
    uint32_t hi = bf16x2_of((v0.z + v1.z) * inv, (v0.w + v1.w) * inv);
    uint2 packed = make_uint2(lo, hi);
    *(uint2*)&g_AOb[(size_t)row * EMB + col] = packed;
}

// ---------------- layernorm ----------------
__global__ __launch_bounds__(256) void ln_kernel(
    const float* __restrict__ gamma, const float* __restrict__ beta,
    float* __restrict__ out)
{
    const int row = blockIdx.x;
    const int tid = threadIdx.x;
    const float* x = g_X + (size_t)row * EMB;
    float4 v = ((const float4*)x)[tid];
    float s = v.x + v.y + v.z + v.w;
    float s2 = v.x * v.x + v.y * v.y + v.z * v.z + v.w * v.w;
#pragma unroll
    for (int w = 1; w < 32; w <<= 1) {
        s += __shfl_xor_sync(0xffffffff, s, w);
        s2 += __shfl_xor_sync(0xffffffff, s2, w);
    }
    __shared__ float sh[16];
    __shared__ float red[2];
    int wid = tid >> 5, lid = tid & 31;
    if (lid == 0) { sh[wid] = s; sh[wid + 8] = s2; }
    __syncthreads();
    if (tid == 0) {
        float ts = 0.f, ts2 = 0.f;
#pragma unroll
        for (int i = 0; i < 8; i++) { ts += sh[i]; ts2 += sh[i + 8]; }
        red[0] = ts; red[1] = ts2;
    }
    __syncthreads();
    float mean = red[0] * (1.0f / EMB);
    float var = red[1] * (1.0f / EMB) - mean * mean;
    float rs = rsqrtf(var + 1e-3f);
    float4 gg = ((const float4*)gamma)[tid];
    float4 bt = ((const float4*)beta)[tid];
    float4 ov;
    ov.x = (v.x - mean) * rs * gg.x + bt.x;
    ov.y = (v.y - mean) * rs * gg.y + bt.y;
    ov.z = (v.z - mean) * rs * gg.z + bt.z;
    ov.w = (v.w - mean) * rs * gg.w + bt.w;
    ((float4*)(out + (size_t)row * EMB))[tid] = ov;
}

// ---------------- launch ----------------
extern "C" void kernel_launch(void* const* d_in, const int* in_sizes, int n_in,
                              void* d_out, int out_size)
{
    const float* w      = (const float*)d_in[0];
    const float* r      = (const float*)d_in[1];
    const float* rwb    = (const float*)d_in[3];
    const float* rrb    = (const float*)d_in[4];
    const float* member = (const float*)d_in[5];
    const float* Wq     = (const float*)d_in[6];
    const float* Wk     = (const float*)d_in[7];
    const float* Wv     = (const float*)d_in[8];
    const float* Wr     = (const float*)d_in[9];
    const float* Wo     = (const float*)d_in[10];
    const float* gamma  = (const float*)d_in[11];
    const float* beta   = (const float*)d_in[12];
    float* out = (float*)d_out;

    dim3 blk(256);

    // 0) prep bf16 A-inputs + transpose/convert weights
    prep_bf16<<<6144, blk>>>(w, member, r);
    transposeW<<<dim3(32, 32, 5), blk>>>(Wq, Wk, Wv, Wr, Wo);

    // 1) ALL projections (Q, fused KV, R) in one launch
    proj_gemm<<<768, blk>>>();

    // 1b) bias.R^T vector (prescaled)
    bbs_kernel<<<128, blk>>>(rrb);

    // 2) BD unshifted (bias-folded, coalesced staged store)
    bd_mma<<<dim3(16, 8, 32), blk>>>();

    // 3) flash attention split-KV (grid 512, dyn smem 96256B)
    static const int FLASH_SMEM = 96256;
    cudaFuncSetAttribute(flash_mma, cudaFuncAttributeMaxDynamicSharedMemorySize, FLASH_SMEM);
    flash_mma<<<dim3(16, NH, BB), blk, FLASH_SMEM>>>(rwb);

    // 3b) combine partials -> bf16 AO
    combine_ao<<<BB * QL, blk>>>();

    // 4) output projection (bf16 A via cp.async) + residual
    wo_gemm<<<dim3(8, 16), blk>>>(w);

    // 5) layernorm
    ln_kernel<<<BB * QL, blk>>>(gamma, beta, out);
}